// round 1
// baseline (speedup 1.0000x reference)
#include <cuda_runtime.h>
#include <math.h>

// ---------------- problem constants ----------------
constexpr int BS      = 2;
constexpr int LQ      = 13294;
constexpr int LV      = 13294;
constexpr int EMB     = 256;
constexpr int NHEAD   = 8;
constexpr int HDIM    = 32;
constexpr int NLVL    = 4;
constexpr int NPTS    = 4;
constexpr int M_ROWS  = BS * LQ;   // 26588

// ---------------- scratch (static device allocs) ----------------
__device__ float g_v   [(size_t)M_ROWS * EMB];   // projected value  [bs*Lv, 256]
__device__ float g_off [(size_t)M_ROWS * EMB];   // sampling offsets [bs*Lq, 256]
__device__ float g_attn[(size_t)M_ROWS * 128];   // attn logits      [bs*Lq, 128]
__device__ float g_mid [(size_t)M_ROWS * EMB];   // sampled output   [bs*Lq, 256]

// ---------------- SGEMM: C[M,N] = A[M,K] * W[N,K]^T + bias[N] ----------------
// 128x128 block tile, BK=8, 256 threads, 8x8 per thread.
#define BM 128
#define BN 128
#define BK 8
#define TM 8
#define TN 8

__global__ __launch_bounds__(256) void sgemm_bias(
    const float* __restrict__ A, const float* __restrict__ W,
    const float* __restrict__ bias, float* __restrict__ C,
    int M, int N, int K)
{
    __shared__ float As[BK][BM];
    __shared__ float Bs[BK][BN];

    const int tid = threadIdx.x;
    const int bm  = blockIdx.y * BM;
    const int bn  = blockIdx.x * BN;

    // global loads: one float4 from A and one from B per thread per k-step
    const int ld_row = tid >> 1;          // 0..127
    const int ld_col = (tid & 1) * 4;     // 0 or 4

    const int tx = tid & 15;              // 0..15
    const int ty = tid >> 4;              // 0..15

    float acc[TM][TN];
    #pragma unroll
    for (int i = 0; i < TM; ++i)
        #pragma unroll
        for (int j = 0; j < TN; ++j) acc[i][j] = 0.f;

    for (int k0 = 0; k0 < K; k0 += BK) {
        // A tile (guard M)
        float4 av;
        const int gm = bm + ld_row;
        if (gm < M) {
            av = *reinterpret_cast<const float4*>(A + (size_t)gm * K + k0 + ld_col);
        } else {
            av = make_float4(0.f, 0.f, 0.f, 0.f);
        }
        As[ld_col + 0][ld_row] = av.x;
        As[ld_col + 1][ld_row] = av.y;
        As[ld_col + 2][ld_row] = av.z;
        As[ld_col + 3][ld_row] = av.w;

        // B tile (N is an exact multiple of BN here)
        const float4 bv = *reinterpret_cast<const float4*>(
            W + (size_t)(bn + ld_row) * K + k0 + ld_col);
        Bs[ld_col + 0][ld_row] = bv.x;
        Bs[ld_col + 1][ld_row] = bv.y;
        Bs[ld_col + 2][ld_row] = bv.z;
        Bs[ld_col + 3][ld_row] = bv.w;

        __syncthreads();

        #pragma unroll
        for (int k = 0; k < BK; ++k) {
            float ra[TM], rb[TN];
            #pragma unroll
            for (int i = 0; i < TM; ++i) ra[i] = As[k][ty * TM + i];
            #pragma unroll
            for (int j = 0; j < TN; ++j) rb[j] = Bs[k][tx * TN + j];
            #pragma unroll
            for (int i = 0; i < TM; ++i)
                #pragma unroll
                for (int j = 0; j < TN; ++j)
                    acc[i][j] = fmaf(ra[i], rb[j], acc[i][j]);
        }
        __syncthreads();
    }

    // epilogue with bias
    #pragma unroll
    for (int i = 0; i < TM; ++i) {
        const int row = bm + ty * TM + i;
        if (row >= M) continue;
        #pragma unroll
        for (int j = 0; j < TN; ++j) {
            const int col = bn + tx * TN + j;
            C[(size_t)row * N + col] = acc[i][j] + bias[col];
        }
    }
}

// ---------------- sampling kernel ----------------
// one block per (b, q): 8 warps = 8 heads, 32 lanes = 32 channels
__global__ __launch_bounds__(256) void sample_kernel(
    const float* __restrict__ v,      // [bs*Lv, 256]  (head-major inner: h*32+c)
    const float* __restrict__ off,    // [bs*Lq, 256]  (h,lvl,p,2)
    const float* __restrict__ attn,   // [bs*Lq, 128]  (h, lvl*4+p)
    const float* __restrict__ ref,    // [bs, Lq, 4, 2]
    const int*   __restrict__ shapes, // [4, 2] (H, W)
    const float* __restrict__ zeta,   // [32]
    float*       __restrict__ out)    // [bs*Lq, 256]
{
    const int m    = blockIdx.x;           // 0..26587 = b*LQ + q
    const int h    = threadIdx.x >> 5;     // head
    const int lane = threadIdx.x & 31;     // channel
    const int b    = (m >= LQ) ? 1 : 0;

    __shared__ int sH[NLVL], sW[NLVL], sStart[NLVL];
    if (threadIdx.x == 0) {
        int st = 0;
        #pragma unroll
        for (int l = 0; l < NLVL; ++l) {
            const int Hh = shapes[2 * l];
            const int Ww = shapes[2 * l + 1];
            sH[l] = Hh; sW[l] = Ww; sStart[l] = st;
            st += Hh * Ww;
        }
    }
    __syncthreads();

    const float* offp  = off  + (size_t)m * 256 + h * 32;
    const float* attnp = attn + (size_t)m * 128 + h * 16;

    // softmax over the 16 logits (redundant per lane; broadcast loads)
    float wgt[16];
    float mx = -1e30f;
    #pragma unroll
    for (int p = 0; p < 16; ++p) { wgt[p] = attnp[p]; mx = fmaxf(mx, wgt[p]); }
    float s = 0.f;
    #pragma unroll
    for (int p = 0; p < 16; ++p) { wgt[p] = __expf(wgt[p] - mx); s += wgt[p]; }
    const float inv = 1.f / s;

    float acc = 0.f;
    const float* vb_head = v + (size_t)b * LV * 256 + h * 32 + lane;

    #pragma unroll
    for (int lvl = 0; lvl < NLVL; ++lvl) {
        const int H = sH[lvl];
        const int W = sW[lvl];
        const float rx = ref[((size_t)m * NLVL + lvl) * 2 + 0];
        const float ry = ref[((size_t)m * NLVL + lvl) * 2 + 1];
        const float* vb = vb_head + (size_t)sStart[lvl] * 256;

        #pragma unroll
        for (int p = 0; p < NPTS; ++p) {
            const int pi = lvl * NPTS + p;
            const float ox = offp[pi * 2 + 0];
            const float oy = offp[pi * 2 + 1];
            // x = ((2*(rx + ox/W) - 1) + 1) * 0.5*W - 0.5  ==  rx*W + ox - 0.5
            const float x = fmaf(rx, (float)W, ox) - 0.5f;
            const float y = fmaf(ry, (float)H, oy) - 0.5f;
            const float x0f = floorf(x);
            const float y0f = floorf(y);
            const float wx = x - x0f;
            const float wy = y - y0f;
            const int x0 = (int)x0f;
            const int y0 = (int)y0f;
            const float a = wgt[pi] * inv;

            const float w00 = (1.f - wx) * (1.f - wy) * a;
            const float w01 = wx * (1.f - wy) * a;
            const float w10 = (1.f - wx) * wy * a;
            const float w11 = wx * wy * a;

            const bool xin0 = (x0 >= 0)     && (x0 < W);
            const bool xin1 = (x0 + 1 >= 0) && (x0 + 1 < W);
            const bool yin0 = (y0 >= 0)     && (y0 < H);
            const bool yin1 = (y0 + 1 >= 0) && (y0 + 1 < H);

            if (xin0 && yin0) acc = fmaf(w00, vb[(size_t)(y0 * W + x0) * 256], acc);
            if (xin1 && yin0) acc = fmaf(w01, vb[(size_t)(y0 * W + x0 + 1) * 256], acc);
            if (xin0 && yin1) acc = fmaf(w10, vb[(size_t)((y0 + 1) * W + x0) * 256], acc);
            if (xin1 && yin1) acc = fmaf(w11, vb[(size_t)((y0 + 1) * W + x0 + 1) * 256], acc);
        }
    }

    out[(size_t)m * 256 + h * 32 + lane] = acc * zeta[lane];
}

// ---------------- launch ----------------
extern "C" void kernel_launch(void* const* d_in, const int* in_sizes, int n_in,
                              void* d_out, int out_size)
{
    const float* query  = (const float*)d_in[0];
    const float* ref    = (const float*)d_in[1];
    const float* value  = (const float*)d_in[2];
    const int*   shapes = (const int*)  d_in[3];
    const float* Wv     = (const float*)d_in[4];
    const float* bv     = (const float*)d_in[5];
    const float* Woff   = (const float*)d_in[6];
    const float* boff   = (const float*)d_in[7];
    const float* Wattn  = (const float*)d_in[8];
    const float* battn  = (const float*)d_in[9];
    const float* Wout   = (const float*)d_in[10];
    const float* bout   = (const float*)d_in[11];
    const float* zeta   = (const float*)d_in[12];
    float*       outp   = (float*)d_out;

    float *pv, *poff, *pattn, *pmid;
    cudaGetSymbolAddress((void**)&pv,    g_v);
    cudaGetSymbolAddress((void**)&poff,  g_off);
    cudaGetSymbolAddress((void**)&pattn, g_attn);
    cudaGetSymbolAddress((void**)&pmid,  g_mid);

    const int M = M_ROWS;
    const int gm = (M + BM - 1) / BM;   // 208

    dim3 blk(256);
    // value projection: [M,256] @ [256,256]^T
    sgemm_bias<<<dim3(EMB / BN, gm), blk>>>(value, Wv, bv, pv, M, EMB, EMB);
    // offsets: [M,256] @ [256,256]^T
    sgemm_bias<<<dim3(EMB / BN, gm), blk>>>(query, Woff, boff, poff, M, EMB, EMB);
    // attn logits: [M,256] @ [128,256]^T
    sgemm_bias<<<dim3(128 / BN, gm), blk>>>(query, Wattn, battn, pattn, M, 128, EMB);
    // sampling
    sample_kernel<<<M, blk>>>(pv, poff, pattn, ref, shapes, zeta, pmid);
    // output projection
    sgemm_bias<<<dim3(EMB / BN, gm), blk>>>(pmid, Wout, bout, outp, M, EMB, EMB);
}

// round 2
// speedup vs baseline: 1.0875x; 1.0875x over previous
#include <cuda_runtime.h>
#include <math.h>

// ---------------- problem constants ----------------
constexpr int BS      = 2;
constexpr int LQ      = 13294;
constexpr int LV      = 13294;
constexpr int EMB     = 256;
constexpr int NLVL    = 4;
constexpr int M_ROWS  = BS * LQ;   // 26588

// ---------------- scratch ----------------
__device__ float g_v   [(size_t)M_ROWS * EMB];
__device__ float g_off [(size_t)M_ROWS * EMB];
__device__ float g_attn[(size_t)M_ROWS * 128];
__device__ float g_mid [(size_t)M_ROWS * EMB];

// ---------------- GEMM config ----------------
constexpr int BM = 128;
constexpr int BN = 128;
constexpr int BK = 16;
constexpr int NIT = EMB / BK;               // 16
constexpr int GM  = (M_ROWS + BM - 1) / BM; // 208

// C[M,N] = A[M,256] * W[N,256]^T + bias, one 128x128 tile per call.
__device__ __forceinline__ void gemm_body(
    const float* __restrict__ A, const float* __restrict__ W,
    const float* __restrict__ bias, float* __restrict__ C,
    int N, int bm, int bn, float* sA, float* sB)
{
    const int tid    = threadIdx.x;
    const int ld_row = tid >> 1;
    const int ld_col = (tid & 1) * 4;
    const int tx     = tid & 15;
    const int ty     = tid >> 4;

    const int arow = min(bm + ld_row, M_ROWS - 1);   // clamp (dup rows, not stored)
    const float* Aptr = A + (size_t)arow * EMB;
    const float* Wptr = W + (size_t)(bn + ld_row) * EMB;

    float4 a0, a1, b0, b1;

    a0 = *reinterpret_cast<const float4*>(Aptr + ld_col);
    a1 = *reinterpret_cast<const float4*>(Aptr + ld_col + 8);
    b0 = *reinterpret_cast<const float4*>(Wptr + ld_col);
    b1 = *reinterpret_cast<const float4*>(Wptr + ld_col + 8);

    {   // store buf 0
        float* As_ = sA;
        float* Bs_ = sB;
        As_[(ld_col+0)*BM + ld_row] = a0.x;
        As_[(ld_col+1)*BM + ld_row] = a0.y;
        As_[(ld_col+2)*BM + ld_row] = a0.z;
        As_[(ld_col+3)*BM + ld_row] = a0.w;
        As_[(ld_col+8)*BM + ld_row] = a1.x;
        As_[(ld_col+9)*BM + ld_row] = a1.y;
        As_[(ld_col+10)*BM + ld_row] = a1.z;
        As_[(ld_col+11)*BM + ld_row] = a1.w;
        Bs_[(ld_col+0)*BN + ld_row] = b0.x;
        Bs_[(ld_col+1)*BN + ld_row] = b0.y;
        Bs_[(ld_col+2)*BN + ld_row] = b0.z;
        Bs_[(ld_col+3)*BN + ld_row] = b0.w;
        Bs_[(ld_col+8)*BN + ld_row] = b1.x;
        Bs_[(ld_col+9)*BN + ld_row] = b1.y;
        Bs_[(ld_col+10)*BN + ld_row] = b1.z;
        Bs_[(ld_col+11)*BN + ld_row] = b1.w;
    }
    __syncthreads();

    float acc[8][8];
    #pragma unroll
    for (int i = 0; i < 8; ++i)
        #pragma unroll
        for (int j = 0; j < 8; ++j) acc[i][j] = 0.f;

    for (int it = 0; it < NIT; ++it) {
        if (it + 1 < NIT) {
            const int k0 = (it + 1) * BK;
            a0 = *reinterpret_cast<const float4*>(Aptr + k0 + ld_col);
            a1 = *reinterpret_cast<const float4*>(Aptr + k0 + ld_col + 8);
            b0 = *reinterpret_cast<const float4*>(Wptr + k0 + ld_col);
            b1 = *reinterpret_cast<const float4*>(Wptr + k0 + ld_col + 8);
        }
        const float* As_ = sA + (it & 1) * BK * BM;
        const float* Bs_ = sB + (it & 1) * BK * BN;
        #pragma unroll
        for (int k = 0; k < BK; ++k) {
            float4 ra0 = *reinterpret_cast<const float4*>(As_ + k*BM + ty*8);
            float4 ra1 = *reinterpret_cast<const float4*>(As_ + k*BM + ty*8 + 4);
            float4 rb0 = *reinterpret_cast<const float4*>(Bs_ + k*BN + tx*8);
            float4 rb1 = *reinterpret_cast<const float4*>(Bs_ + k*BN + tx*8 + 4);
            float ra[8] = {ra0.x, ra0.y, ra0.z, ra0.w, ra1.x, ra1.y, ra1.z, ra1.w};
            float rb[8] = {rb0.x, rb0.y, rb0.z, rb0.w, rb1.x, rb1.y, rb1.z, rb1.w};
            #pragma unroll
            for (int i = 0; i < 8; ++i)
                #pragma unroll
                for (int j = 0; j < 8; ++j)
                    acc[i][j] = fmaf(ra[i], rb[j], acc[i][j]);
        }
        if (it + 1 < NIT) {
            const int buf = (it + 1) & 1;
            float* As_w = sA + buf * BK * BM;
            float* Bs_w = sB + buf * BK * BN;
            As_w[(ld_col+0)*BM + ld_row] = a0.x;
            As_w[(ld_col+1)*BM + ld_row] = a0.y;
            As_w[(ld_col+2)*BM + ld_row] = a0.z;
            As_w[(ld_col+3)*BM + ld_row] = a0.w;
            As_w[(ld_col+8)*BM + ld_row] = a1.x;
            As_w[(ld_col+9)*BM + ld_row] = a1.y;
            As_w[(ld_col+10)*BM + ld_row] = a1.z;
            As_w[(ld_col+11)*BM + ld_row] = a1.w;
            Bs_w[(ld_col+0)*BN + ld_row] = b0.x;
            Bs_w[(ld_col+1)*BN + ld_row] = b0.y;
            Bs_w[(ld_col+2)*BN + ld_row] = b0.z;
            Bs_w[(ld_col+3)*BN + ld_row] = b0.w;
            Bs_w[(ld_col+8)*BN + ld_row] = b1.x;
            Bs_w[(ld_col+9)*BN + ld_row] = b1.y;
            Bs_w[(ld_col+10)*BN + ld_row] = b1.z;
            Bs_w[(ld_col+11)*BN + ld_row] = b1.w;
            __syncthreads();
        }
    }

    // epilogue
    #pragma unroll
    for (int i = 0; i < 8; ++i) {
        const int row = bm + ty * 8 + i;
        if (row >= M_ROWS) continue;
        const int col = bn + tx * 8;
        float4 o0, o1;
        o0.x = acc[i][0] + bias[col + 0];
        o0.y = acc[i][1] + bias[col + 1];
        o0.z = acc[i][2] + bias[col + 2];
        o0.w = acc[i][3] + bias[col + 3];
        o1.x = acc[i][4] + bias[col + 4];
        o1.y = acc[i][5] + bias[col + 5];
        o1.z = acc[i][6] + bias[col + 6];
        o1.w = acc[i][7] + bias[col + 7];
        *reinterpret_cast<float4*>(C + (size_t)row * N + col)     = o0;
        *reinterpret_cast<float4*>(C + (size_t)row * N + col + 4) = o1;
    }
}

// fused: value-proj (416 blocks) + offsets (416) + attn (208) = 1040 blocks
__global__ __launch_bounds__(256, 2) void gemm_fused3(
    const float* __restrict__ value, const float* __restrict__ query,
    const float* __restrict__ Wv,    const float* __restrict__ bv,
    const float* __restrict__ Woff,  const float* __restrict__ boff,
    const float* __restrict__ Wattn, const float* __restrict__ battn,
    float* __restrict__ pv, float* __restrict__ poff, float* __restrict__ pattn)
{
    __shared__ float sA[2 * BK * BM];
    __shared__ float sB[2 * BK * BN];
    const int id = blockIdx.x;
    const float *A, *W, *bias; float* C; int N, local;
    if (id < 2 * GM)      { A = value; W = Wv;    bias = bv;    C = pv;    N = 256; local = id; }
    else if (id < 4 * GM) { A = query; W = Woff;  bias = boff;  C = poff;  N = 256; local = id - 2*GM; }
    else                  { A = query; W = Wattn; bias = battn; C = pattn; N = 128; local = id - 4*GM; }
    const int gx = N / BN;
    const int by = local / gx;
    const int bx = local - by * gx;
    gemm_body(A, W, bias, C, N, by * BM, bx * BN, sA, sB);
}

__global__ __launch_bounds__(256, 2) void gemm_single(
    const float* __restrict__ A, const float* __restrict__ W,
    const float* __restrict__ bias, float* __restrict__ C)
{
    __shared__ float sA[2 * BK * BM];
    __shared__ float sB[2 * BK * BN];
    const int by = blockIdx.x >> 1;
    const int bx = blockIdx.x & 1;
    gemm_body(A, W, bias, C, 256, by * BM, bx * BN, sA, sB);
}

// ---------------- sampling kernel ----------------
// one block per m: 8 warps = 8 heads.
// Phase 1: lanes 0-15 compute per-point softmax weight + 4 (weight, index)
// corner entries (OOB folded into zero weight, clamped index) -> smem.
// Phase 2: all 32 lanes run a branch-free 64-entry gather/FMA loop.
__global__ __launch_bounds__(256) void sample_kernel(
    const float* __restrict__ v,      // [bs*Lv, 256]
    const float* __restrict__ off,    // [bs*Lq, 256]
    const float* __restrict__ attn,   // [bs*Lq, 128]
    const float* __restrict__ ref,    // [bs, Lq, 4, 2]
    const int*   __restrict__ shapes, // [4, 2]
    const float* __restrict__ zeta,   // [32]
    float*       __restrict__ out)    // [bs*Lq, 256]
{
    __shared__ float2 ent[8 * 64];

    const int m    = blockIdx.x;
    const int warp = threadIdx.x >> 5;   // head
    const int lane = threadIdx.x & 31;
    const int b    = (m >= LQ) ? 1 : 0;

    // ---- phase 1 ----
    const int p   = lane & 15;
    const int lvl = p >> 2;

    const float* attnp = attn + (size_t)m * 128 + warp * 16;
    float logit = attnp[p];
    float mx = logit;
    #pragma unroll
    for (int o = 8; o; o >>= 1) mx = fmaxf(mx, __shfl_xor_sync(0xffffffffu, mx, o));
    float e = __expf(logit - mx);
    float ssum = e;
    #pragma unroll
    for (int o = 8; o; o >>= 1) ssum += __shfl_xor_sync(0xffffffffu, ssum, o);
    const float a = e / ssum;

    if (lane < 16) {
        const int h0 = shapes[0], w0 = shapes[1];
        const int h1 = shapes[2], w1 = shapes[3];
        const int h2 = shapes[4], w2 = shapes[5];
        const int h3 = shapes[6], w3 = shapes[7];
        const int s1 = h0 * w0;
        const int s2 = s1 + h1 * w1;
        const int s3 = s2 + h2 * w2;

        const int H     = (lvl == 0) ? h0 : (lvl == 1) ? h1 : (lvl == 2) ? h2 : h3;
        const int W     = (lvl == 0) ? w0 : (lvl == 1) ? w1 : (lvl == 2) ? w2 : w3;
        const int start = (lvl == 0) ? 0  : (lvl == 1) ? s1 : (lvl == 2) ? s2 : s3;

        const float rx = ref[((size_t)m * NLVL + lvl) * 2 + 0];
        const float ry = ref[((size_t)m * NLVL + lvl) * 2 + 1];
        const float* offp = off + (size_t)m * 256 + warp * 32;
        const float ox = offp[2 * p + 0];
        const float oy = offp[2 * p + 1];

        // x = rx*W + ox - 0.5 (normalize/denormalize cancels)
        const float x = fmaf(rx, (float)W, ox) - 0.5f;
        const float y = fmaf(ry, (float)H, oy) - 0.5f;
        const float x0f = floorf(x);
        const float y0f = floorf(y);
        const float wx = x - x0f;
        const float wy = y - y0f;
        const int x0 = (int)x0f;
        const int y0 = (int)y0f;

        const bool vx0 = (x0 >= 0)     && (x0 < W);
        const bool vx1 = (x0 + 1 >= 0) && (x0 + 1 < W);
        const bool vy0 = (y0 >= 0)     && (y0 < H);
        const bool vy1 = (y0 + 1 >= 0) && (y0 + 1 < H);

        const int x0c = min(max(x0, 0), W - 1);
        const int x1c = min(max(x0 + 1, 0), W - 1);
        const int y0c = min(max(y0, 0), H - 1);
        const int y1c = min(max(y0 + 1, 0), H - 1);

        const float w00 = (vx0 && vy0) ? (1.f - wx) * (1.f - wy) * a : 0.f;
        const float w01 = (vx1 && vy0) ? wx * (1.f - wy) * a : 0.f;
        const float w10 = (vx0 && vy1) ? (1.f - wx) * wy * a : 0.f;
        const float w11 = (vx1 && vy1) ? wx * wy * a : 0.f;

        const int rowbase = b * LV + start;
        const int hoff    = warp * 32;
        const int i00 = ((rowbase + y0c * W + x0c) << 8) + hoff;
        const int i01 = ((rowbase + y0c * W + x1c) << 8) + hoff;
        const int i10 = ((rowbase + y1c * W + x0c) << 8) + hoff;
        const int i11 = ((rowbase + y1c * W + x1c) << 8) + hoff;

        float2* ep = ent + warp * 64 + p * 4;
        ep[0] = make_float2(w00, __int_as_float(i00));
        ep[1] = make_float2(w01, __int_as_float(i01));
        ep[2] = make_float2(w10, __int_as_float(i10));
        ep[3] = make_float2(w11, __int_as_float(i11));
    }
    __syncwarp();

    // ---- phase 2 ----
    const float2* eptr = ent + warp * 64;
    const float* vl = v + lane;
    float acc = 0.f;
    #pragma unroll 8
    for (int i = 0; i < 64; ++i) {
        const float2 eentry = eptr[i];
        acc = fmaf(eentry.x, vl[__float_as_int(eentry.y)], acc);
    }

    out[(size_t)m * 256 + warp * 32 + lane] = acc * zeta[lane];
}

// ---------------- launch ----------------
extern "C" void kernel_launch(void* const* d_in, const int* in_sizes, int n_in,
                              void* d_out, int out_size)
{
    const float* query  = (const float*)d_in[0];
    const float* ref    = (const float*)d_in[1];
    const float* value  = (const float*)d_in[2];
    const int*   shapes = (const int*)  d_in[3];
    const float* Wv     = (const float*)d_in[4];
    const float* bv     = (const float*)d_in[5];
    const float* Woff   = (const float*)d_in[6];
    const float* boff   = (const float*)d_in[7];
    const float* Wattn  = (const float*)d_in[8];
    const float* battn  = (const float*)d_in[9];
    const float* Wout   = (const float*)d_in[10];
    const float* bout   = (const float*)d_in[11];
    const float* zeta   = (const float*)d_in[12];
    float*       outp   = (float*)d_out;

    float *pv, *poff, *pattn, *pmid;
    cudaGetSymbolAddress((void**)&pv,    g_v);
    cudaGetSymbolAddress((void**)&poff,  g_off);
    cudaGetSymbolAddress((void**)&pattn, g_attn);
    cudaGetSymbolAddress((void**)&pmid,  g_mid);

    dim3 blk(256);
    gemm_fused3<<<5 * GM, blk>>>(value, query, Wv, bv, Woff, boff,
                                 Wattn, battn, pv, poff, pattn);
    sample_kernel<<<M_ROWS, blk>>>(pv, poff, pattn, ref, shapes, zeta, pmid);
    gemm_single<<<2 * GM, blk>>>(pmid, Wout, bout, outp);
}

// round 3
// speedup vs baseline: 2.3136x; 2.1274x over previous
#include <cuda_runtime.h>
#include <math.h>

// ---------------- problem constants ----------------
constexpr int BS      = 2;
constexpr int LQ      = 13294;
constexpr int LV      = 13294;
constexpr int EMB     = 256;
constexpr int NLVL    = 4;
constexpr int M_ROWS  = BS * LQ;   // 26588

// ---------------- scratch ----------------
__device__ float g_v   [(size_t)M_ROWS * EMB];
__device__ float g_off [(size_t)M_ROWS * EMB];
__device__ float g_attn[(size_t)M_ROWS * 128];
__device__ float g_mid [(size_t)M_ROWS * EMB];

// ---------------- tensor-core GEMM config ----------------
// C[M,N] = A[M,256] * W[N,256]^T + bias.  Block tile 128x128, BK=32,
// 512 threads = 16 warps, each warp a 32x32 tile (2 m-frags x 4 n-frags
// of mma.m16n8k8.tf32).
constexpr int TBM  = 128;
constexpr int SROW = 44;                      // smem row stride (floats), bank-clean
constexpr int GM   = (M_ROWS + TBM - 1) / TBM; // 208

__device__ __forceinline__ unsigned f2tf(float x) {
    unsigned r;
    asm("cvt.rna.tf32.f32 %0, %1;" : "=r"(r) : "f"(x));
    return r;
}

__device__ __forceinline__ void mma_tf32(float4& d,
    unsigned a0, unsigned a1, unsigned a2, unsigned a3,
    unsigned b0, unsigned b1)
{
    asm volatile(
        "mma.sync.aligned.m16n8k8.row.col.f32.tf32.tf32.f32 "
        "{%0,%1,%2,%3},{%4,%5,%6,%7},{%8,%9},{%0,%1,%2,%3};"
        : "+f"(d.x), "+f"(d.y), "+f"(d.z), "+f"(d.w)
        : "r"(a0), "r"(a1), "r"(a2), "r"(a3), "r"(b0), "r"(b1));
}

// one 128x128 output tile
__device__ __forceinline__ void gemm_tile(
    const float* __restrict__ A, const float* __restrict__ W,
    const float* __restrict__ bias, float* __restrict__ C,
    int N, int bm, int bn, float* As, float* Bs)
{
    const int tid  = threadIdx.x;
    const int warp = tid >> 5;
    const int lane = tid & 31;
    const int g    = lane >> 2;   // groupID
    const int c    = lane & 3;    // threadID_in_group
    const int wm   = (warp >> 2) * 32;   // warp m offset in tile
    const int wn   = (warp & 3)  * 32;   // warp n offset in tile

    float4 acc[2][4];
    #pragma unroll
    for (int mf = 0; mf < 2; ++mf)
        #pragma unroll
        for (int nf = 0; nf < 4; ++nf)
            acc[mf][nf] = make_float4(0.f, 0.f, 0.f, 0.f);

    #pragma unroll 1
    for (int kc = 0; kc < 8; ++kc) {
        const int k0 = kc * 32;
        // ---- stage global -> smem with tf32 round + k-permutation ----
        // element (row, k_local = q*4 + comp) -> smem[row*SROW + comp*8 + q]
        #pragma unroll
        for (int t = 0; t < 2; ++t) {
            const int f   = tid + t * 512;   // float4 index, 0..1023
            const int row = f >> 3;
            const int q   = f & 7;
            const int ar  = min(bm + row, M_ROWS - 1);
            const float4 av = *reinterpret_cast<const float4*>(
                A + (size_t)ar * EMB + k0 + q * 4);
            float* da = As + row * SROW + q;
            da[0]  = __uint_as_float(f2tf(av.x));
            da[8]  = __uint_as_float(f2tf(av.y));
            da[16] = __uint_as_float(f2tf(av.z));
            da[24] = __uint_as_float(f2tf(av.w));
            const float4 bv = *reinterpret_cast<const float4*>(
                W + (size_t)(bn + row) * EMB + k0 + q * 4);
            float* db = Bs + row * SROW + q;
            db[0]  = __uint_as_float(f2tf(bv.x));
            db[8]  = __uint_as_float(f2tf(bv.y));
            db[16] = __uint_as_float(f2tf(bv.z));
            db[24] = __uint_as_float(f2tf(bv.w));
        }
        __syncthreads();

        // ---- fragment loads (2x LDS.128 per row) ----
        float aR[4][8];   // rows wm + g + {0,8,16,24}
        float bR[4][8];   // rows wn + g + nf*8
        #pragma unroll
        for (int ri = 0; ri < 4; ++ri) {
            const float4* p = reinterpret_cast<const float4*>(
                As + (wm + g + ri * 8) * SROW + c * 8);
            *reinterpret_cast<float4*>(&aR[ri][0]) = p[0];
            *reinterpret_cast<float4*>(&aR[ri][4]) = p[1];
        }
        #pragma unroll
        for (int nf = 0; nf < 4; ++nf) {
            const float4* p = reinterpret_cast<const float4*>(
                Bs + (wn + g + nf * 8) * SROW + c * 8);
            *reinterpret_cast<float4*>(&bR[nf][0]) = p[0];
            *reinterpret_cast<float4*>(&bR[nf][4]) = p[1];
        }

        // ---- 32 HMMAs per warp per chunk ----
        #pragma unroll
        for (int j = 0; j < 4; ++j) {
            #pragma unroll
            for (int mf = 0; mf < 2; ++mf) {
                const unsigned a0 = __float_as_uint(aR[2*mf  ][2*j  ]);
                const unsigned a1 = __float_as_uint(aR[2*mf+1][2*j  ]);
                const unsigned a2 = __float_as_uint(aR[2*mf  ][2*j+1]);
                const unsigned a3 = __float_as_uint(aR[2*mf+1][2*j+1]);
                #pragma unroll
                for (int nf = 0; nf < 4; ++nf) {
                    mma_tf32(acc[mf][nf], a0, a1, a2, a3,
                             __float_as_uint(bR[nf][2*j]),
                             __float_as_uint(bR[nf][2*j+1]));
                }
            }
        }
        __syncthreads();
    }

    // ---- epilogue with bias ----
    #pragma unroll
    for (int mf = 0; mf < 2; ++mf) {
        const int row = bm + wm + mf * 16 + g;
        #pragma unroll
        for (int nf = 0; nf < 4; ++nf) {
            const int col = bn + wn + nf * 8 + c * 2;
            const float b0 = bias[col];
            const float b1 = bias[col + 1];
            const float4 v = acc[mf][nf];
            if (row < M_ROWS) {
                float2 o = make_float2(v.x + b0, v.y + b1);
                *reinterpret_cast<float2*>(C + (size_t)row * N + col) = o;
            }
            if (row + 8 < M_ROWS) {
                float2 o = make_float2(v.z + b0, v.w + b1);
                *reinterpret_cast<float2*>(C + (size_t)(row + 8) * N + col) = o;
            }
        }
    }
}

// fused: value-proj (2*GM tiles) + offsets (2*GM) + attn (GM) = 5*GM blocks
__global__ __launch_bounds__(512) void gemm_fused3_tc(
    const float* __restrict__ value, const float* __restrict__ query,
    const float* __restrict__ Wv,    const float* __restrict__ bv,
    const float* __restrict__ Woff,  const float* __restrict__ boff,
    const float* __restrict__ Wattn, const float* __restrict__ battn,
    float* __restrict__ pv, float* __restrict__ poff, float* __restrict__ pattn)
{
    __shared__ float As[TBM * SROW];
    __shared__ float Bs[TBM * SROW];
    const int id = blockIdx.x;
    const float *A, *W, *bias; float* C; int N, local;
    if (id < 2 * GM)      { A = value; W = Wv;    bias = bv;    C = pv;    N = 256; local = id; }
    else if (id < 4 * GM) { A = query; W = Woff;  bias = boff;  C = poff;  N = 256; local = id - 2*GM; }
    else                  { A = query; W = Wattn; bias = battn; C = pattn; N = 128; local = id - 4*GM; }
    const int gx = N / 128;
    const int by = local / gx;
    const int bx = local - by * gx;
    gemm_tile(A, W, bias, C, N, by * TBM, bx * 128, As, Bs);
}

__global__ __launch_bounds__(512) void gemm_out_tc(
    const float* __restrict__ A, const float* __restrict__ W,
    const float* __restrict__ bias, float* __restrict__ C)
{
    __shared__ float As[TBM * SROW];
    __shared__ float Bs[TBM * SROW];
    const int by = blockIdx.x >> 1;
    const int bx = blockIdx.x & 1;
    gemm_tile(A, W, bias, C, 256, by * TBM, bx * 128, As, Bs);
}

// ---------------- sampling kernel (unchanged from round 2) ----------------
__global__ __launch_bounds__(256) void sample_kernel(
    const float* __restrict__ v,
    const float* __restrict__ off,
    const float* __restrict__ attn,
    const float* __restrict__ ref,
    const int*   __restrict__ shapes,
    const float* __restrict__ zeta,
    float*       __restrict__ out)
{
    __shared__ float2 ent[8 * 64];

    const int m    = blockIdx.x;
    const int warp = threadIdx.x >> 5;
    const int lane = threadIdx.x & 31;
    const int b    = (m >= LQ) ? 1 : 0;

    const int p   = lane & 15;
    const int lvl = p >> 2;

    const float* attnp = attn + (size_t)m * 128 + warp * 16;
    float logit = attnp[p];
    float mx = logit;
    #pragma unroll
    for (int o = 8; o; o >>= 1) mx = fmaxf(mx, __shfl_xor_sync(0xffffffffu, mx, o));
    float e = __expf(logit - mx);
    float ssum = e;
    #pragma unroll
    for (int o = 8; o; o >>= 1) ssum += __shfl_xor_sync(0xffffffffu, ssum, o);
    const float a = e / ssum;

    if (lane < 16) {
        const int h0 = shapes[0], w0 = shapes[1];
        const int h1 = shapes[2], w1 = shapes[3];
        const int h2 = shapes[4], w2 = shapes[5];
        const int h3 = shapes[6], w3 = shapes[7];
        const int s1 = h0 * w0;
        const int s2 = s1 + h1 * w1;
        const int s3 = s2 + h2 * w2;

        const int H     = (lvl == 0) ? h0 : (lvl == 1) ? h1 : (lvl == 2) ? h2 : h3;
        const int W     = (lvl == 0) ? w0 : (lvl == 1) ? w1 : (lvl == 2) ? w2 : w3;
        const int start = (lvl == 0) ? 0  : (lvl == 1) ? s1 : (lvl == 2) ? s2 : s3;

        const float rx = ref[((size_t)m * NLVL + lvl) * 2 + 0];
        const float ry = ref[((size_t)m * NLVL + lvl) * 2 + 1];
        const float* offp = off + (size_t)m * 256 + warp * 32;
        const float ox = offp[2 * p + 0];
        const float oy = offp[2 * p + 1];

        const float x = fmaf(rx, (float)W, ox) - 0.5f;
        const float y = fmaf(ry, (float)H, oy) - 0.5f;
        const float x0f = floorf(x);
        const float y0f = floorf(y);
        const float wx = x - x0f;
        const float wy = y - y0f;
        const int x0 = (int)x0f;
        const int y0 = (int)y0f;

        const bool vx0 = (x0 >= 0)     && (x0 < W);
        const bool vx1 = (x0 + 1 >= 0) && (x0 + 1 < W);
        const bool vy0 = (y0 >= 0)     && (y0 < H);
        const bool vy1 = (y0 + 1 >= 0) && (y0 + 1 < H);

        const int x0c = min(max(x0, 0), W - 1);
        const int x1c = min(max(x0 + 1, 0), W - 1);
        const int y0c = min(max(y0, 0), H - 1);
        const int y1c = min(max(y0 + 1, 0), H - 1);

        const float w00 = (vx0 && vy0) ? (1.f - wx) * (1.f - wy) * a : 0.f;
        const float w01 = (vx1 && vy0) ? wx * (1.f - wy) * a : 0.f;
        const float w10 = (vx0 && vy1) ? (1.f - wx) * wy * a : 0.f;
        const float w11 = (vx1 && vy1) ? wx * wy * a : 0.f;

        const int rowbase = b * LV + start;
        const int hoff    = warp * 32;
        const int i00 = ((rowbase + y0c * W + x0c) << 8) + hoff;
        const int i01 = ((rowbase + y0c * W + x1c) << 8) + hoff;
        const int i10 = ((rowbase + y1c * W + x0c) << 8) + hoff;
        const int i11 = ((rowbase + y1c * W + x1c) << 8) + hoff;

        float2* ep = ent + warp * 64 + p * 4;
        ep[0] = make_float2(w00, __int_as_float(i00));
        ep[1] = make_float2(w01, __int_as_float(i01));
        ep[2] = make_float2(w10, __int_as_float(i10));
        ep[3] = make_float2(w11, __int_as_float(i11));
    }
    __syncwarp();

    const float2* eptr = ent + warp * 64;
    const float* vl = v + lane;
    float acc = 0.f;
    #pragma unroll 8
    for (int i = 0; i < 64; ++i) {
        const float2 eentry = eptr[i];
        acc = fmaf(eentry.x, vl[__float_as_int(eentry.y)], acc);
    }

    out[(size_t)m * 256 + warp * 32 + lane] = acc * zeta[lane];
}

// ---------------- launch ----------------
extern "C" void kernel_launch(void* const* d_in, const int* in_sizes, int n_in,
                              void* d_out, int out_size)
{
    const float* query  = (const float*)d_in[0];
    const float* ref    = (const float*)d_in[1];
    const float* value  = (const float*)d_in[2];
    const int*   shapes = (const int*)  d_in[3];
    const float* Wv     = (const float*)d_in[4];
    const float* bv     = (const float*)d_in[5];
    const float* Woff   = (const float*)d_in[6];
    const float* boff   = (const float*)d_in[7];
    const float* Wattn  = (const float*)d_in[8];
    const float* battn  = (const float*)d_in[9];
    const float* Wout   = (const float*)d_in[10];
    const float* bout   = (const float*)d_in[11];
    const float* zeta   = (const float*)d_in[12];
    float*       outp   = (float*)d_out;

    float *pv, *poff, *pattn, *pmid;
    cudaGetSymbolAddress((void**)&pv,    g_v);
    cudaGetSymbolAddress((void**)&poff,  g_off);
    cudaGetSymbolAddress((void**)&pattn, g_attn);
    cudaGetSymbolAddress((void**)&pmid,  g_mid);

    gemm_fused3_tc<<<5 * GM, 512>>>(value, query, Wv, bv, Woff, boff,
                                    Wattn, battn, pv, poff, pattn);
    sample_kernel<<<M_ROWS, 256>>>(pv, poff, pattn, ref, shapes, zeta, pmid);
    gemm_out_tc<<<2 * GM, 512>>>(pmid, Wout, bout, outp);
}

// round 4
// speedup vs baseline: 2.6780x; 1.1575x over previous
#include <cuda_runtime.h>
#include <math.h>

// ---------------- problem constants ----------------
constexpr int BS      = 2;
constexpr int LQ      = 13294;
constexpr int LV      = 13294;
constexpr int EMB     = 256;
constexpr int NLVL    = 4;
constexpr int M_ROWS  = BS * LQ;   // 26588

// ---------------- scratch ----------------
__device__ float g_v   [(size_t)M_ROWS * EMB];
__device__ float g_off [(size_t)M_ROWS * EMB];
__device__ float g_attn[(size_t)M_ROWS * 128];
__device__ float g_mid [(size_t)M_ROWS * EMB];

// ---------------- tensor-core GEMM config ----------------
constexpr int TBM  = 128;
constexpr int SROW = 44;                       // smem row stride (floats)
constexpr int BUF  = TBM * SROW;               // one buffer (floats)
constexpr int GM   = (M_ROWS + TBM - 1) / TBM; // 208
constexpr size_t SMEM_BYTES = (size_t)4 * BUF * sizeof(float); // 2 bufs x (A,B)

__device__ __forceinline__ unsigned f2tf(float x) {
    unsigned r;
    asm("cvt.rna.tf32.f32 %0, %1;" : "=r"(r) : "f"(x));
    return r;
}

__device__ __forceinline__ void mma_tf32(float4& d,
    unsigned a0, unsigned a1, unsigned a2, unsigned a3,
    unsigned b0, unsigned b1)
{
    asm volatile(
        "mma.sync.aligned.m16n8k8.row.col.f32.tf32.tf32.f32 "
        "{%0,%1,%2,%3},{%4,%5,%6,%7},{%8,%9},{%0,%1,%2,%3};"
        : "+f"(d.x), "+f"(d.y), "+f"(d.z), "+f"(d.w)
        : "r"(a0), "r"(a1), "r"(a2), "r"(a3), "r"(b0), "r"(b1));
}

// stage one (row,q) float4 pair into permuted smem: k_local = q*4+comp ->
// pos comp*8 + q
__device__ __forceinline__ void stage4(float* dst, int row, int q, float4 v) {
    float* d = dst + row * SROW + q;
    d[0]  = __uint_as_float(f2tf(v.x));
    d[8]  = __uint_as_float(f2tf(v.y));
    d[16] = __uint_as_float(f2tf(v.z));
    d[24] = __uint_as_float(f2tf(v.w));
}

// one 128x128 output tile, double-buffered, 512 threads
__device__ __forceinline__ void gemm_tile(
    const float* __restrict__ A, const float* __restrict__ W,
    const float* __restrict__ bias, float* __restrict__ C,
    int N, int bm, int bn, float* As, float* Bs)
{
    const int tid  = threadIdx.x;
    const int warp = tid >> 5;
    const int lane = tid & 31;
    const int g    = lane >> 2;
    const int c    = lane & 3;
    const int wm   = (warp >> 2) * 32;
    const int wn   = (warp & 3)  * 32;

    // staging coordinates (two float4s per array per thread per chunk)
    const int r0 = tid >> 3,          q0 = tid & 7;
    const int r1 = (tid + 512) >> 3,  q1 = (tid + 512) & 7;
    const float* Ap0 = A + (size_t)min(bm + r0, M_ROWS - 1) * EMB + q0 * 4;
    const float* Ap1 = A + (size_t)min(bm + r1, M_ROWS - 1) * EMB + q1 * 4;
    const float* Wp0 = W + (size_t)(bn + r0) * EMB + q0 * 4;
    const float* Wp1 = W + (size_t)(bn + r1) * EMB + q1 * 4;

    float4 acc[2][4];
    #pragma unroll
    for (int mf = 0; mf < 2; ++mf)
        #pragma unroll
        for (int nf = 0; nf < 4; ++nf)
            acc[mf][nf] = make_float4(0.f, 0.f, 0.f, 0.f);

    float4 va0, va1, vb0, vb1;
    // prologue: chunk 0 -> buf 0
    va0 = *reinterpret_cast<const float4*>(Ap0);
    va1 = *reinterpret_cast<const float4*>(Ap1);
    vb0 = *reinterpret_cast<const float4*>(Wp0);
    vb1 = *reinterpret_cast<const float4*>(Wp1);
    stage4(As, r0, q0, va0);
    stage4(As, r1, q1, va1);
    stage4(Bs, r0, q0, vb0);
    stage4(Bs, r1, q1, vb1);
    __syncthreads();

    #pragma unroll 1
    for (int kc = 0; kc < 8; ++kc) {
        // prefetch next chunk
        if (kc < 7) {
            const int k0 = (kc + 1) * 32;
            va0 = *reinterpret_cast<const float4*>(Ap0 + k0);
            va1 = *reinterpret_cast<const float4*>(Ap1 + k0);
            vb0 = *reinterpret_cast<const float4*>(Wp0 + k0);
            vb1 = *reinterpret_cast<const float4*>(Wp1 + k0);
        }

        const float* Ab = As + (kc & 1) * BUF;
        const float* Bb = Bs + (kc & 1) * BUF;

        float aR[4][8];
        float bR[4][8];
        #pragma unroll
        for (int ri = 0; ri < 4; ++ri) {
            const float4* p = reinterpret_cast<const float4*>(
                Ab + (wm + g + ri * 8) * SROW + c * 8);
            *reinterpret_cast<float4*>(&aR[ri][0]) = p[0];
            *reinterpret_cast<float4*>(&aR[ri][4]) = p[1];
        }
        #pragma unroll
        for (int nf = 0; nf < 4; ++nf) {
            const float4* p = reinterpret_cast<const float4*>(
                Bb + (wn + g + nf * 8) * SROW + c * 8);
            *reinterpret_cast<float4*>(&bR[nf][0]) = p[0];
            *reinterpret_cast<float4*>(&bR[nf][4]) = p[1];
        }

        #pragma unroll
        for (int j = 0; j < 4; ++j) {
            #pragma unroll
            for (int mf = 0; mf < 2; ++mf) {
                const unsigned a0 = __float_as_uint(aR[2*mf  ][2*j  ]);
                const unsigned a1 = __float_as_uint(aR[2*mf+1][2*j  ]);
                const unsigned a2 = __float_as_uint(aR[2*mf  ][2*j+1]);
                const unsigned a3 = __float_as_uint(aR[2*mf+1][2*j+1]);
                #pragma unroll
                for (int nf = 0; nf < 4; ++nf) {
                    mma_tf32(acc[mf][nf], a0, a1, a2, a3,
                             __float_as_uint(bR[nf][2*j]),
                             __float_as_uint(bR[nf][2*j+1]));
                }
            }
        }

        if (kc < 7) {
            float* Aw = As + ((kc + 1) & 1) * BUF;
            float* Bw = Bs + ((kc + 1) & 1) * BUF;
            stage4(Aw, r0, q0, va0);
            stage4(Aw, r1, q1, va1);
            stage4(Bw, r0, q0, vb0);
            stage4(Bw, r1, q1, vb1);
            __syncthreads();
        }
    }

    // epilogue with bias
    #pragma unroll
    for (int mf = 0; mf < 2; ++mf) {
        const int row = bm + wm + mf * 16 + g;
        #pragma unroll
        for (int nf = 0; nf < 4; ++nf) {
            const int col = bn + wn + nf * 8 + c * 2;
            const float b0 = bias[col];
            const float b1 = bias[col + 1];
            const float4 v = acc[mf][nf];
            if (row < M_ROWS) {
                float2 o = make_float2(v.x + b0, v.y + b1);
                *reinterpret_cast<float2*>(C + (size_t)row * N + col) = o;
            }
            if (row + 8 < M_ROWS) {
                float2 o = make_float2(v.z + b0, v.w + b1);
                *reinterpret_cast<float2*>(C + (size_t)(row + 8) * N + col) = o;
            }
        }
    }
}

__global__ __launch_bounds__(512) void gemm_fused3_tc(
    const float* __restrict__ value, const float* __restrict__ query,
    const float* __restrict__ Wv,    const float* __restrict__ bv,
    const float* __restrict__ Woff,  const float* __restrict__ boff,
    const float* __restrict__ Wattn, const float* __restrict__ battn,
    float* __restrict__ pv, float* __restrict__ poff, float* __restrict__ pattn)
{
    extern __shared__ float smem[];
    float* As = smem;
    float* Bs = smem + 2 * BUF;
    const int id = blockIdx.x;
    const float *A, *W, *bias; float* C; int N, local;
    if (id < 2 * GM)      { A = value; W = Wv;    bias = bv;    C = pv;    N = 256; local = id; }
    else if (id < 4 * GM) { A = query; W = Woff;  bias = boff;  C = poff;  N = 256; local = id - 2*GM; }
    else                  { A = query; W = Wattn; bias = battn; C = pattn; N = 128; local = id - 4*GM; }
    const int gx = N / 128;
    const int by = local / gx;
    const int bx = local - by * gx;
    gemm_tile(A, W, bias, C, N, by * TBM, bx * 128, As, Bs);
}

__global__ __launch_bounds__(512) void gemm_out_tc(
    const float* __restrict__ A, const float* __restrict__ W,
    const float* __restrict__ bias, float* __restrict__ C)
{
    extern __shared__ float smem[];
    float* As = smem;
    float* Bs = smem + 2 * BUF;
    const int by = blockIdx.x >> 1;
    const int bx = blockIdx.x & 1;
    gemm_tile(A, W, bias, C, 256, by * TBM, bx * 128, As, Bs);
}

// ---------------- sampling kernel ----------------
// Phase 1 (lanes 0-15): softmax + 4 (weight,index) corner entries -> smem.
// Phase 2: split warp — lanes 0-15 even corners, 16-31 odd corners, each
// lane gathers a float2 (2 channels) per corner -> LDG.64, half the LDG
// instruction count; shuffle-combine the two halves at the end.
__global__ __launch_bounds__(256) void sample_kernel(
    const float* __restrict__ v,
    const float* __restrict__ off,
    const float* __restrict__ attn,
    const float* __restrict__ ref,
    const int*   __restrict__ shapes,
    const float* __restrict__ zeta,
    float*       __restrict__ out)
{
    __shared__ float2 ent[8 * 64];

    const int m    = blockIdx.x;
    const int warp = threadIdx.x >> 5;
    const int lane = threadIdx.x & 31;
    const int b    = (m >= LQ) ? 1 : 0;

    const int p   = lane & 15;
    const int lvl = p >> 2;

    const float* attnp = attn + (size_t)m * 128 + warp * 16;
    float logit = attnp[p];
    float mx = logit;
    #pragma unroll
    for (int o = 8; o; o >>= 1) mx = fmaxf(mx, __shfl_xor_sync(0xffffffffu, mx, o));
    float e = __expf(logit - mx);
    float ssum = e;
    #pragma unroll
    for (int o = 8; o; o >>= 1) ssum += __shfl_xor_sync(0xffffffffu, ssum, o);
    const float a = e / ssum;

    if (lane < 16) {
        const int h0 = shapes[0], w0 = shapes[1];
        const int h1 = shapes[2], w1 = shapes[3];
        const int h2 = shapes[4], w2 = shapes[5];
        const int h3 = shapes[6], w3 = shapes[7];
        const int s1 = h0 * w0;
        const int s2 = s1 + h1 * w1;
        const int s3 = s2 + h2 * w2;

        const int H     = (lvl == 0) ? h0 : (lvl == 1) ? h1 : (lvl == 2) ? h2 : h3;
        const int W     = (lvl == 0) ? w0 : (lvl == 1) ? w1 : (lvl == 2) ? w2 : w3;
        const int start = (lvl == 0) ? 0  : (lvl == 1) ? s1 : (lvl == 2) ? s2 : s3;

        const float rx = ref[((size_t)m * NLVL + lvl) * 2 + 0];
        const float ry = ref[((size_t)m * NLVL + lvl) * 2 + 1];
        const float* offp = off + (size_t)m * 256 + warp * 32;
        const float ox = offp[2 * p + 0];
        const float oy = offp[2 * p + 1];

        const float x = fmaf(rx, (float)W, ox) - 0.5f;
        const float y = fmaf(ry, (float)H, oy) - 0.5f;
        const float x0f = floorf(x);
        const float y0f = floorf(y);
        const float wx = x - x0f;
        const float wy = y - y0f;
        const int x0 = (int)x0f;
        const int y0 = (int)y0f;

        const bool vx0 = (x0 >= 0)     && (x0 < W);
        const bool vx1 = (x0 + 1 >= 0) && (x0 + 1 < W);
        const bool vy0 = (y0 >= 0)     && (y0 < H);
        const bool vy1 = (y0 + 1 >= 0) && (y0 + 1 < H);

        const int x0c = min(max(x0, 0), W - 1);
        const int x1c = min(max(x0 + 1, 0), W - 1);
        const int y0c = min(max(y0, 0), H - 1);
        const int y1c = min(max(y0 + 1, 0), H - 1);

        const float w00 = (vx0 && vy0) ? (1.f - wx) * (1.f - wy) * a : 0.f;
        const float w01 = (vx1 && vy0) ? wx * (1.f - wy) * a : 0.f;
        const float w10 = (vx0 && vy1) ? (1.f - wx) * wy * a : 0.f;
        const float w11 = (vx1 && vy1) ? wx * wy * a : 0.f;

        const int rowbase = b * LV + start;
        const int hoff    = warp * 32;
        const int i00 = ((rowbase + y0c * W + x0c) << 8) + hoff;
        const int i01 = ((rowbase + y0c * W + x1c) << 8) + hoff;
        const int i10 = ((rowbase + y1c * W + x0c) << 8) + hoff;
        const int i11 = ((rowbase + y1c * W + x1c) << 8) + hoff;

        float2* ep = ent + warp * 64 + p * 4;
        ep[0] = make_float2(w00, __int_as_float(i00));
        ep[1] = make_float2(w01, __int_as_float(i01));
        ep[2] = make_float2(w10, __int_as_float(i10));
        ep[3] = make_float2(w11, __int_as_float(i11));
    }
    __syncwarp();

    // ---- phase 2: split-warp float2 gathers ----
    const int half = lane >> 4;        // 0: even corners, 1: odd corners
    const int hl   = lane & 15;        // channel pair owner
    const float2* eptr = ent + warp * 64 + half;
    const float* vbase = v + 2 * hl;

    float accx = 0.f, accy = 0.f;
    #pragma unroll 8
    for (int i = 0; i < 32; ++i) {
        const float2 eentry = eptr[2 * i];
        const float2 val = *reinterpret_cast<const float2*>(
            vbase + __float_as_int(eentry.y));
        accx = fmaf(eentry.x, val.x, accx);
        accy = fmaf(eentry.x, val.y, accy);
    }
    accx += __shfl_down_sync(0xffffffffu, accx, 16);
    accy += __shfl_down_sync(0xffffffffu, accy, 16);

    if (lane < 16) {
        float2 o;
        o.x = accx * zeta[2 * hl];
        o.y = accy * zeta[2 * hl + 1];
        *reinterpret_cast<float2*>(out + (size_t)m * 256 + warp * 32 + 2 * hl) = o;
    }
}

// ---------------- launch ----------------
extern "C" void kernel_launch(void* const* d_in, const int* in_sizes, int n_in,
                              void* d_out, int out_size)
{
    const float* query  = (const float*)d_in[0];
    const float* ref    = (const float*)d_in[1];
    const float* value  = (const float*)d_in[2];
    const int*   shapes = (const int*)  d_in[3];
    const float* Wv     = (const float*)d_in[4];
    const float* bv     = (const float*)d_in[5];
    const float* Woff   = (const float*)d_in[6];
    const float* boff   = (const float*)d_in[7];
    const float* Wattn  = (const float*)d_in[8];
    const float* battn  = (const float*)d_in[9];
    const float* Wout   = (const float*)d_in[10];
    const float* bout   = (const float*)d_in[11];
    const float* zeta   = (const float*)d_in[12];
    float*       outp   = (float*)d_out;

    float *pv, *poff, *pattn, *pmid;
    cudaGetSymbolAddress((void**)&pv,    g_v);
    cudaGetSymbolAddress((void**)&poff,  g_off);
    cudaGetSymbolAddress((void**)&pattn, g_attn);
    cudaGetSymbolAddress((void**)&pmid,  g_mid);

    // opt-in to >48KB dynamic smem (idempotent, not a stream op)
    cudaFuncSetAttribute(gemm_fused3_tc,
        cudaFuncAttributeMaxDynamicSharedMemorySize, (int)SMEM_BYTES);
    cudaFuncSetAttribute(gemm_out_tc,
        cudaFuncAttributeMaxDynamicSharedMemorySize, (int)SMEM_BYTES);

    gemm_fused3_tc<<<5 * GM, 512, SMEM_BYTES>>>(value, query, Wv, bv, Woff, boff,
                                                Wattn, battn, pv, poff, pattn);
    sample_kernel<<<M_ROWS, 256>>>(pv, poff, pattn, ref, shapes, zeta, pmid);
    gemm_out_tc<<<2 * GM, 512, SMEM_BYTES>>>(pmid, Wout, bout, outp);
}

// round 5
// speedup vs baseline: 2.7702x; 1.0344x over previous
#include <cuda_runtime.h>
#include <math.h>

// ---------------- problem constants ----------------
constexpr int BS      = 2;
constexpr int LQ      = 13294;
constexpr int LV      = 13294;
constexpr int EMB     = 256;
constexpr int NLVL    = 4;
constexpr int M_ROWS  = BS * LQ;   // 26588

// ---------------- scratch ----------------
__device__ float g_v    [(size_t)M_ROWS * EMB];   // value-proj out (fp32, plain)
__device__ float g_off  [(size_t)M_ROWS * EMB];   // offsets out (fp32, plain)
__device__ float g_attn [(size_t)M_ROWS * 128];   // attn logits (fp32, plain)
__device__ float g_vp   [(size_t)M_ROWS * EMB];   // value input, tf32 permuted
__device__ float g_qp   [(size_t)M_ROWS * EMB];   // query input, tf32 permuted
__device__ float g_midp [(size_t)M_ROWS * EMB];   // sampled mid, tf32 permuted
__device__ float g_wp   [(size_t)896 * EMB];      // all weights, tf32 permuted

// ---------------- GEMM config ----------------
// block tile 128(M) x 64(N), BK=32, 256 threads = 8 warps (4 m x 2 n), each
// warp 32x32.  tf32 HMMA m16n8k8.  A/W pre-converted+permuted in global:
// element k (kc = k>>5, kl = k&31, q = kl>>2, comp = kl&3) lives at
// row*256 + kc*32 + comp*8 + q.
constexpr int TBM  = 128;
constexpr int TBN  = 64;
constexpr int SROW = 44;                         // smem row stride (floats)
constexpr int ABUF = TBM * SROW;
constexpr int BBUF = TBN * SROW;
constexpr int GM   = (M_ROWS + TBM - 1) / TBM;   // 208
constexpr size_t SMEM_BYTES = (size_t)2 * (ABUF + BBUF) * sizeof(float);

__device__ __forceinline__ unsigned f2tf(float x) {
    unsigned r;
    asm("cvt.rna.tf32.f32 %0, %1;" : "=r"(r) : "f"(x));
    return r;
}

__device__ __forceinline__ void mma_tf32(float4& d,
    unsigned a0, unsigned a1, unsigned a2, unsigned a3,
    unsigned b0, unsigned b1)
{
    asm volatile(
        "mma.sync.aligned.m16n8k8.row.col.f32.tf32.tf32.f32 "
        "{%0,%1,%2,%3},{%4,%5,%6,%7},{%8,%9},{%0,%1,%2,%3};"
        : "+f"(d.x), "+f"(d.y), "+f"(d.z), "+f"(d.w)
        : "r"(a0), "r"(a1), "r"(a2), "r"(a3), "r"(b0), "r"(b1));
}

// ---------------- prep kernels ----------------
// weights: rows 0-255 Wv, 256-511 Woff, 512-639 Wattn, 640-895 Wout
__global__ __launch_bounds__(64) void prep_w(
    const float* __restrict__ Wv,   const float* __restrict__ Woff,
    const float* __restrict__ Wattn,const float* __restrict__ Wout,
    float* __restrict__ gwp)
{
    const int r = blockIdx.x;
    const int t = threadIdx.x;        // 0..63
    const float* src; int lr;
    if (r < 256)      { src = Wv;    lr = r; }
    else if (r < 512) { src = Woff;  lr = r - 256; }
    else if (r < 640) { src = Wattn; lr = r - 512; }
    else              { src = Wout;  lr = r - 640; }
    const float4 v = *reinterpret_cast<const float4*>(src + (size_t)lr * 256 + t * 4);
    const int kc = t >> 3, q = t & 7;
    float* d = gwp + (size_t)r * 256 + kc * 32 + q;
    d[0]  = __uint_as_float(f2tf(v.x));
    d[8]  = __uint_as_float(f2tf(v.y));
    d[16] = __uint_as_float(f2tf(v.z));
    d[24] = __uint_as_float(f2tf(v.w));
}

__global__ __launch_bounds__(256) void prep_a(
    const float* __restrict__ value, const float* __restrict__ query,
    float* __restrict__ gvp, float* __restrict__ gqp)
{
    const int total = 2 * M_ROWS * 64;   // float4 count
    for (int f = blockIdx.x * blockDim.x + threadIdx.x; f < total;
         f += gridDim.x * blockDim.x) {
        int row = f >> 6;
        const int t = f & 63;
        const float* src; float* dst;
        if (row < M_ROWS) { src = value; dst = gvp; }
        else              { src = query; dst = gqp; row -= M_ROWS; }
        const float4 v = *reinterpret_cast<const float4*>(
            src + (size_t)row * 256 + t * 4);
        const int kc = t >> 3, q = t & 7;
        float* d = dst + (size_t)row * 256 + kc * 32 + q;
        d[0]  = __uint_as_float(f2tf(v.x));
        d[8]  = __uint_as_float(f2tf(v.y));
        d[16] = __uint_as_float(f2tf(v.z));
        d[24] = __uint_as_float(f2tf(v.w));
    }
}

// ---------------- GEMM tile body ----------------
// A: permuted tf32 [M,256]; Wp: permuted tf32 rows; bias fp32; C fp32 [.,N]
__device__ __forceinline__ void gemm_tile(
    const float* __restrict__ A, const float* __restrict__ Wp,
    const float* __restrict__ bias, float* __restrict__ C,
    int N, int bm, int bn, float* As, float* Bs)
{
    const int tid  = threadIdx.x;
    const int warp = tid >> 5;
    const int lane = tid & 31;
    const int g    = lane >> 2;
    const int c    = lane & 3;
    const int wm   = (warp >> 1) * 32;   // 0,32,64,96
    const int wn   = (warp & 1)  * 32;   // 0,32

    // staging: A = 1024 float4 (4/thread), B = 512 float4 (2/thread)
    const int ar[4] = { tid, tid + 256, tid + 512, tid + 768 };
    const float* Aptr[4]; int Adst[4];
    #pragma unroll
    for (int i = 0; i < 4; ++i) {
        const int row = ar[i] >> 3, s = ar[i] & 7;
        Aptr[i] = A + (size_t)min(bm + row, M_ROWS - 1) * 256 + s * 4;
        Adst[i] = row * SROW + s * 4;
    }
    const float* Wptr[2]; int Bdst[2];
    #pragma unroll
    for (int i = 0; i < 2; ++i) {
        const int f = tid + i * 256;
        const int row = f >> 3, s = f & 7;
        Wptr[i] = Wp + (size_t)(bn + row) * 256 + s * 4;
        Bdst[i] = row * SROW + s * 4;
    }

    float4 acc[2][2];
    #pragma unroll
    for (int mf = 0; mf < 2; ++mf)
        #pragma unroll
        for (int nf = 0; nf < 2; ++nf)
            acc[mf][nf] = make_float4(0.f, 0.f, 0.f, 0.f);
    // warp tile is 32x32 = 2 m-frags x 4 n-frags; acc2 holds other 2 n-frags
    float4 acc2[2][2];
    #pragma unroll
    for (int mf = 0; mf < 2; ++mf)
        #pragma unroll
        for (int nf = 0; nf < 2; ++nf)
            acc2[mf][nf] = make_float4(0.f, 0.f, 0.f, 0.f);

    float4 pa[4], pb[2];
    // prologue: chunk 0 -> buf 0
    #pragma unroll
    for (int i = 0; i < 4; ++i) pa[i] = *reinterpret_cast<const float4*>(Aptr[i]);
    #pragma unroll
    for (int i = 0; i < 2; ++i) pb[i] = *reinterpret_cast<const float4*>(Wptr[i]);
    #pragma unroll
    for (int i = 0; i < 4; ++i) *reinterpret_cast<float4*>(As + Adst[i]) = pa[i];
    #pragma unroll
    for (int i = 0; i < 2; ++i) *reinterpret_cast<float4*>(Bs + Bdst[i]) = pb[i];
    __syncthreads();

    #pragma unroll 1
    for (int kc = 0; kc < 8; ++kc) {
        if (kc < 7) {
            const int k0 = (kc + 1) * 32;
            #pragma unroll
            for (int i = 0; i < 4; ++i)
                pa[i] = *reinterpret_cast<const float4*>(Aptr[i] + k0);
            #pragma unroll
            for (int i = 0; i < 2; ++i)
                pb[i] = *reinterpret_cast<const float4*>(Wptr[i] + k0);
        }

        const float* Ab = As + (kc & 1) * ABUF;
        const float* Bb = Bs + (kc & 1) * BBUF;

        #pragma unroll
        for (int half = 0; half < 2; ++half) {
            float aF[4][4];
            float bF[4][4];
            #pragma unroll
            for (int ri = 0; ri < 4; ++ri)
                *reinterpret_cast<float4*>(aF[ri]) =
                    *reinterpret_cast<const float4*>(
                        Ab + (wm + g + ri * 8) * SROW + c * 8 + half * 4);
            #pragma unroll
            for (int nf = 0; nf < 4; ++nf)
                *reinterpret_cast<float4*>(bF[nf]) =
                    *reinterpret_cast<const float4*>(
                        Bb + (wn + g + nf * 8) * SROW + c * 8 + half * 4);

            #pragma unroll
            for (int j2 = 0; j2 < 2; ++j2) {
                #pragma unroll
                for (int mf = 0; mf < 2; ++mf) {
                    const unsigned a0 = __float_as_uint(aF[2*mf  ][2*j2  ]);
                    const unsigned a1 = __float_as_uint(aF[2*mf+1][2*j2  ]);
                    const unsigned a2 = __float_as_uint(aF[2*mf  ][2*j2+1]);
                    const unsigned a3 = __float_as_uint(aF[2*mf+1][2*j2+1]);
                    #pragma unroll
                    for (int nf = 0; nf < 2; ++nf) {
                        mma_tf32(acc[mf][nf], a0, a1, a2, a3,
                                 __float_as_uint(bF[nf][2*j2]),
                                 __float_as_uint(bF[nf][2*j2+1]));
                        mma_tf32(acc2[mf][nf], a0, a1, a2, a3,
                                 __float_as_uint(bF[nf+2][2*j2]),
                                 __float_as_uint(bF[nf+2][2*j2+1]));
                    }
                }
            }
        }

        if (kc < 7) {
            float* Aw = As + ((kc + 1) & 1) * ABUF;
            float* Bw = Bs + ((kc + 1) & 1) * BBUF;
            #pragma unroll
            for (int i = 0; i < 4; ++i)
                *reinterpret_cast<float4*>(Aw + Adst[i]) = pa[i];
            #pragma unroll
            for (int i = 0; i < 2; ++i)
                *reinterpret_cast<float4*>(Bw + Bdst[i]) = pb[i];
            __syncthreads();
        }
    }

    // epilogue with bias
    #pragma unroll
    for (int mf = 0; mf < 2; ++mf) {
        const int row = bm + wm + mf * 16 + g;
        #pragma unroll
        for (int nf = 0; nf < 4; ++nf) {
            const float4 v = (nf < 2) ? acc[mf][nf] : acc2[mf][nf - 2];
            const int col = bn + wn + nf * 8 + c * 2;
            const float b0 = bias[col];
            const float b1 = bias[col + 1];
            if (row < M_ROWS) {
                float2 o = make_float2(v.x + b0, v.y + b1);
                *reinterpret_cast<float2*>(C + (size_t)row * N + col) = o;
            }
            if (row + 8 < M_ROWS) {
                float2 o = make_float2(v.z + b0, v.w + b1);
                *reinterpret_cast<float2*>(C + (size_t)(row + 8) * N + col) = o;
            }
        }
    }
}

// fused: value (4*GM) + offsets (4*GM) + attn (2*GM) = 10*GM blocks
__global__ __launch_bounds__(256, 2) void gemm_fused3_tc(
    const float* __restrict__ gvp, const float* __restrict__ gqp,
    const float* __restrict__ gwp,
    const float* __restrict__ bv, const float* __restrict__ boff,
    const float* __restrict__ battn,
    float* __restrict__ pv, float* __restrict__ poff, float* __restrict__ pattn)
{
    extern __shared__ float smem[];
    float* As = smem;
    float* Bs = smem + 2 * ABUF;
    const int id = blockIdx.x;
    const float *A, *W, *bias; float* C; int N, local;
    if (id < 4 * GM)      { A = gvp; W = gwp;             bias = bv;    C = pv;    N = 256; local = id; }
    else if (id < 8 * GM) { A = gqp; W = gwp + 256 * 256; bias = boff;  C = poff;  N = 256; local = id - 4*GM; }
    else                  { A = gqp; W = gwp + 512 * 256; bias = battn; C = pattn; N = 128; local = id - 8*GM; }
    const int gx = N / TBN;
    const int by = local / gx;
    const int bx = local - by * gx;
    gemm_tile(A, W, bias, C, N, by * TBM, bx * TBN, As, Bs);
}

__global__ __launch_bounds__(256, 2) void gemm_out_tc(
    const float* __restrict__ gmidp, const float* __restrict__ gwp,
    const float* __restrict__ bias, float* __restrict__ C)
{
    extern __shared__ float smem[];
    float* As = smem;
    float* Bs = smem + 2 * ABUF;
    const int by = blockIdx.x >> 2;
    const int bx = blockIdx.x & 3;
    gemm_tile(gmidp, gwp + 640 * 256, bias, C, 256, by * TBM, bx * TBN, As, Bs);
}

// ---------------- sampling kernel ----------------
__global__ __launch_bounds__(256) void sample_kernel(
    const float* __restrict__ v,
    const float* __restrict__ off,
    const float* __restrict__ attn,
    const float* __restrict__ ref,
    const int*   __restrict__ shapes,
    const float* __restrict__ zeta,
    float*       __restrict__ outp)   // permuted tf32 mid
{
    __shared__ float2 ent[8 * 64];

    const int m    = blockIdx.x;
    const int warp = threadIdx.x >> 5;
    const int lane = threadIdx.x & 31;
    const int b    = (m >= LQ) ? 1 : 0;

    const int p   = lane & 15;
    const int lvl = p >> 2;

    const float* attnp = attn + (size_t)m * 128 + warp * 16;
    float logit = attnp[p];
    float mx = logit;
    #pragma unroll
    for (int o = 8; o; o >>= 1) mx = fmaxf(mx, __shfl_xor_sync(0xffffffffu, mx, o));
    float e = __expf(logit - mx);
    float ssum = e;
    #pragma unroll
    for (int o = 8; o; o >>= 1) ssum += __shfl_xor_sync(0xffffffffu, ssum, o);
    const float a = e / ssum;

    if (lane < 16) {
        const int h0 = shapes[0], w0 = shapes[1];
        const int h1 = shapes[2], w1 = shapes[3];
        const int h2 = shapes[4], w2 = shapes[5];
        const int h3 = shapes[6], w3 = shapes[7];
        const int s1 = h0 * w0;
        const int s2 = s1 + h1 * w1;
        const int s3 = s2 + h2 * w2;

        const int H     = (lvl == 0) ? h0 : (lvl == 1) ? h1 : (lvl == 2) ? h2 : h3;
        const int W     = (lvl == 0) ? w0 : (lvl == 1) ? w1 : (lvl == 2) ? w2 : w3;
        const int start = (lvl == 0) ? 0  : (lvl == 1) ? s1 : (lvl == 2) ? s2 : s3;

        const float rx = ref[((size_t)m * NLVL + lvl) * 2 + 0];
        const float ry = ref[((size_t)m * NLVL + lvl) * 2 + 1];
        const float* offp = off + (size_t)m * 256 + warp * 32;
        const float ox = offp[2 * p + 0];
        const float oy = offp[2 * p + 1];

        const float x = fmaf(rx, (float)W, ox) - 0.5f;
        const float y = fmaf(ry, (float)H, oy) - 0.5f;
        const float x0f = floorf(x);
        const float y0f = floorf(y);
        const float wx = x - x0f;
        const float wy = y - y0f;
        const int x0 = (int)x0f;
        const int y0 = (int)y0f;

        const bool vx0 = (x0 >= 0)     && (x0 < W);
        const bool vx1 = (x0 + 1 >= 0) && (x0 + 1 < W);
        const bool vy0 = (y0 >= 0)     && (y0 < H);
        const bool vy1 = (y0 + 1 >= 0) && (y0 + 1 < H);

        const int x0c = min(max(x0, 0), W - 1);
        const int x1c = min(max(x0 + 1, 0), W - 1);
        const int y0c = min(max(y0, 0), H - 1);
        const int y1c = min(max(y0 + 1, 0), H - 1);

        const float w00 = (vx0 && vy0) ? (1.f - wx) * (1.f - wy) * a : 0.f;
        const float w01 = (vx1 && vy0) ? wx * (1.f - wy) * a : 0.f;
        const float w10 = (vx0 && vy1) ? (1.f - wx) * wy * a : 0.f;
        const float w11 = (vx1 && vy1) ? wx * wy * a : 0.f;

        const int rowbase = b * LV + start;
        const int hoff    = warp * 32;
        const int i00 = ((rowbase + y0c * W + x0c) << 8) + hoff;
        const int i01 = ((rowbase + y0c * W + x1c) << 8) + hoff;
        const int i10 = ((rowbase + y1c * W + x0c) << 8) + hoff;
        const int i11 = ((rowbase + y1c * W + x1c) << 8) + hoff;

        float2* ep = ent + warp * 64 + p * 4;
        ep[0] = make_float2(w00, __int_as_float(i00));
        ep[1] = make_float2(w01, __int_as_float(i01));
        ep[2] = make_float2(w10, __int_as_float(i10));
        ep[3] = make_float2(w11, __int_as_float(i11));
    }
    __syncwarp();

    // split-warp float2 gathers
    const int half = lane >> 4;
    const int hl   = lane & 15;
    const float2* eptr = ent + warp * 64 + half;
    const float* vbase = v + 2 * hl;

    float accx = 0.f, accy = 0.f;
    #pragma unroll 8
    for (int i = 0; i < 32; ++i) {
        const float2 eentry = eptr[2 * i];
        const float2 val = *reinterpret_cast<const float2*>(
            vbase + __float_as_int(eentry.y));
        accx = fmaf(eentry.x, val.x, accx);
        accy = fmaf(eentry.x, val.y, accy);
    }
    accx += __shfl_down_sync(0xffffffffu, accx, 16);
    accy += __shfl_down_sync(0xffffffffu, accy, 16);

    if (lane < 16) {
        // channels c0 = warp*32 + 2*hl, c1 = c0+1; store permuted tf32:
        // kl = 2*hl+e -> q = hl>>1, comp = 2*(hl&1)+e
        const float ox = accx * zeta[2 * hl];
        const float oy = accy * zeta[2 * hl + 1];
        float* dst = outp + (size_t)m * 256 + warp * 32 + (hl >> 1);
        const int comp0 = 2 * (hl & 1);
        dst[(comp0)     * 8] = __uint_as_float(f2tf(ox));
        dst[(comp0 + 1) * 8] = __uint_as_float(f2tf(oy));
    }
}

// ---------------- launch ----------------
extern "C" void kernel_launch(void* const* d_in, const int* in_sizes, int n_in,
                              void* d_out, int out_size)
{
    const float* query  = (const float*)d_in[0];
    const float* ref    = (const float*)d_in[1];
    const float* value  = (const float*)d_in[2];
    const int*   shapes = (const int*)  d_in[3];
    const float* Wv     = (const float*)d_in[4];
    const float* bv     = (const float*)d_in[5];
    const float* Woff   = (const float*)d_in[6];
    const float* boff   = (const float*)d_in[7];
    const float* Wattn  = (const float*)d_in[8];
    const float* battn  = (const float*)d_in[9];
    const float* Wout   = (const float*)d_in[10];
    const float* bout   = (const float*)d_in[11];
    const float* zeta   = (const float*)d_in[12];
    float*       outp   = (float*)d_out;

    float *pv, *poff, *pattn, *pvp, *pqp, *pmidp, *pwp;
    cudaGetSymbolAddress((void**)&pv,    g_v);
    cudaGetSymbolAddress((void**)&poff,  g_off);
    cudaGetSymbolAddress((void**)&pattn, g_attn);
    cudaGetSymbolAddress((void**)&pvp,   g_vp);
    cudaGetSymbolAddress((void**)&pqp,   g_qp);
    cudaGetSymbolAddress((void**)&pmidp, g_midp);
    cudaGetSymbolAddress((void**)&pwp,   g_wp);

    cudaFuncSetAttribute(gemm_fused3_tc,
        cudaFuncAttributeMaxDynamicSharedMemorySize, (int)SMEM_BYTES);
    cudaFuncSetAttribute(gemm_out_tc,
        cudaFuncAttributeMaxDynamicSharedMemorySize, (int)SMEM_BYTES);

    prep_w<<<896, 64>>>(Wv, Woff, Wattn, Wout, pwp);
    prep_a<<<2080, 256>>>(value, query, pvp, pqp);
    gemm_fused3_tc<<<10 * GM, 256, SMEM_BYTES>>>(pvp, pqp, pwp, bv, boff, battn,
                                                 pv, poff, pattn);
    sample_kernel<<<M_ROWS, 256>>>(pv, poff, pattn, ref, shapes, zeta, pmidp);
    gemm_out_tc<<<4 * GM, 256, SMEM_BYTES>>>(pmidp, pwp, bout, outp);
}

// round 6
// speedup vs baseline: 2.8693x; 1.0358x over previous
#include <cuda_runtime.h>
#include <math.h>

// ---------------- problem constants ----------------
constexpr int BS      = 2;
constexpr int LQ      = 13294;
constexpr int LV      = 13294;
constexpr int EMB     = 256;
constexpr int NLVL    = 4;
constexpr int M_ROWS  = BS * LQ;   // 26588

// ---------------- scratch ----------------
__device__ float g_v    [(size_t)M_ROWS * EMB];   // value-proj out (fp32, plain)
__device__ float g_off  [(size_t)M_ROWS * EMB];   // offsets out (fp32, plain)
__device__ float g_attn [(size_t)M_ROWS * 128];   // attn logits (fp32, plain)
__device__ float g_vp   [(size_t)M_ROWS * EMB];   // value input, tf32 permuted
__device__ float g_qp   [(size_t)M_ROWS * EMB];   // query input, tf32 permuted
__device__ float g_midp [(size_t)M_ROWS * EMB];   // sampled mid, tf32 permuted
__device__ float g_wp   [(size_t)896 * EMB];      // all weights, tf32 permuted

// ---------------- GEMM config ----------------
constexpr int TBM  = 128;
constexpr int TBN  = 64;
constexpr int SROW = 44;
constexpr int ABUF = TBM * SROW;
constexpr int BBUF = TBN * SROW;
constexpr int GM   = (M_ROWS + TBM - 1) / TBM;   // 208
constexpr size_t SMEM_BYTES = (size_t)2 * (ABUF + BBUF) * sizeof(float);

__device__ __forceinline__ unsigned f2tf(float x) {
    unsigned r;
    asm("cvt.rna.tf32.f32 %0, %1;" : "=r"(r) : "f"(x));
    return r;
}

__device__ __forceinline__ void mma_tf32(float4& d,
    unsigned a0, unsigned a1, unsigned a2, unsigned a3,
    unsigned b0, unsigned b1)
{
    asm volatile(
        "mma.sync.aligned.m16n8k8.row.col.f32.tf32.tf32.f32 "
        "{%0,%1,%2,%3},{%4,%5,%6,%7},{%8,%9},{%0,%1,%2,%3};"
        : "+f"(d.x), "+f"(d.y), "+f"(d.z), "+f"(d.w)
        : "r"(a0), "r"(a1), "r"(a2), "r"(a3), "r"(b0), "r"(b1));
}

// ---------------- prep kernels ----------------
__global__ __launch_bounds__(64) void prep_w(
    const float* __restrict__ Wv,   const float* __restrict__ Woff,
    const float* __restrict__ Wattn,const float* __restrict__ Wout,
    float* __restrict__ gwp)
{
    const int r = blockIdx.x;
    const int t = threadIdx.x;
    const float* src; int lr;
    if (r < 256)      { src = Wv;    lr = r; }
    else if (r < 512) { src = Woff;  lr = r - 256; }
    else if (r < 640) { src = Wattn; lr = r - 512; }
    else              { src = Wout;  lr = r - 640; }
    const float4 v = *reinterpret_cast<const float4*>(src + (size_t)lr * 256 + t * 4);
    const int kc = t >> 3, q = t & 7;
    float* d = gwp + (size_t)r * 256 + kc * 32 + q;
    d[0]  = __uint_as_float(f2tf(v.x));
    d[8]  = __uint_as_float(f2tf(v.y));
    d[16] = __uint_as_float(f2tf(v.z));
    d[24] = __uint_as_float(f2tf(v.w));
}

__global__ __launch_bounds__(256) void prep_a(
    const float* __restrict__ value, const float* __restrict__ query,
    float* __restrict__ gvp, float* __restrict__ gqp)
{
    const int total = 2 * M_ROWS * 64;
    for (int f = blockIdx.x * blockDim.x + threadIdx.x; f < total;
         f += gridDim.x * blockDim.x) {
        int row = f >> 6;
        const int t = f & 63;
        const float* src; float* dst;
        if (row < M_ROWS) { src = value; dst = gvp; }
        else              { src = query; dst = gqp; row -= M_ROWS; }
        const float4 v = *reinterpret_cast<const float4*>(
            src + (size_t)row * 256 + t * 4);
        const int kc = t >> 3, q = t & 7;
        float* d = dst + (size_t)row * 256 + kc * 32 + q;
        d[0]  = __uint_as_float(f2tf(v.x));
        d[8]  = __uint_as_float(f2tf(v.y));
        d[16] = __uint_as_float(f2tf(v.z));
        d[24] = __uint_as_float(f2tf(v.w));
    }
}

// ---------------- GEMM tile body ----------------
__device__ __forceinline__ void gemm_tile(
    const float* __restrict__ A, const float* __restrict__ Wp,
    const float* __restrict__ bias, float* __restrict__ C,
    int N, int bm, int bn, float* As, float* Bs)
{
    const int tid  = threadIdx.x;
    const int warp = tid >> 5;
    const int lane = tid & 31;
    const int g    = lane >> 2;
    const int c    = lane & 3;
    const int wm   = (warp >> 1) * 32;
    const int wn   = (warp & 1)  * 32;

    const int ar[4] = { tid, tid + 256, tid + 512, tid + 768 };
    const float* Aptr[4]; int Adst[4];
    #pragma unroll
    for (int i = 0; i < 4; ++i) {
        const int row = ar[i] >> 3, s = ar[i] & 7;
        Aptr[i] = A + (size_t)min(bm + row, M_ROWS - 1) * 256 + s * 4;
        Adst[i] = row * SROW + s * 4;
    }
    const float* Wptr[2]; int Bdst[2];
    #pragma unroll
    for (int i = 0; i < 2; ++i) {
        const int f = tid + i * 256;
        const int row = f >> 3, s = f & 7;
        Wptr[i] = Wp + (size_t)(bn + row) * 256 + s * 4;
        Bdst[i] = row * SROW + s * 4;
    }

    float4 acc[2][2], acc2[2][2];
    #pragma unroll
    for (int mf = 0; mf < 2; ++mf)
        #pragma unroll
        for (int nf = 0; nf < 2; ++nf) {
            acc[mf][nf]  = make_float4(0.f, 0.f, 0.f, 0.f);
            acc2[mf][nf] = make_float4(0.f, 0.f, 0.f, 0.f);
        }

    float4 pa[4], pb[2];
    #pragma unroll
    for (int i = 0; i < 4; ++i) pa[i] = *reinterpret_cast<const float4*>(Aptr[i]);
    #pragma unroll
    for (int i = 0; i < 2; ++i) pb[i] = *reinterpret_cast<const float4*>(Wptr[i]);
    #pragma unroll
    for (int i = 0; i < 4; ++i) *reinterpret_cast<float4*>(As + Adst[i]) = pa[i];
    #pragma unroll
    for (int i = 0; i < 2; ++i) *reinterpret_cast<float4*>(Bs + Bdst[i]) = pb[i];
    __syncthreads();

    #pragma unroll 1
    for (int kc = 0; kc < 8; ++kc) {
        if (kc < 7) {
            const int k0 = (kc + 1) * 32;
            #pragma unroll
            for (int i = 0; i < 4; ++i)
                pa[i] = *reinterpret_cast<const float4*>(Aptr[i] + k0);
            #pragma unroll
            for (int i = 0; i < 2; ++i)
                pb[i] = *reinterpret_cast<const float4*>(Wptr[i] + k0);
        }

        const float* Ab = As + (kc & 1) * ABUF;
        const float* Bb = Bs + (kc & 1) * BBUF;

        #pragma unroll
        for (int half = 0; half < 2; ++half) {
            float aF[4][4];
            float bF[4][4];
            #pragma unroll
            for (int ri = 0; ri < 4; ++ri)
                *reinterpret_cast<float4*>(aF[ri]) =
                    *reinterpret_cast<const float4*>(
                        Ab + (wm + g + ri * 8) * SROW + c * 8 + half * 4);
            #pragma unroll
            for (int nf = 0; nf < 4; ++nf)
                *reinterpret_cast<float4*>(bF[nf]) =
                    *reinterpret_cast<const float4*>(
                        Bb + (wn + g + nf * 8) * SROW + c * 8 + half * 4);

            #pragma unroll
            for (int j2 = 0; j2 < 2; ++j2) {
                #pragma unroll
                for (int mf = 0; mf < 2; ++mf) {
                    const unsigned a0 = __float_as_uint(aF[2*mf  ][2*j2  ]);
                    const unsigned a1 = __float_as_uint(aF[2*mf+1][2*j2  ]);
                    const unsigned a2 = __float_as_uint(aF[2*mf  ][2*j2+1]);
                    const unsigned a3 = __float_as_uint(aF[2*mf+1][2*j2+1]);
                    #pragma unroll
                    for (int nf = 0; nf < 2; ++nf) {
                        mma_tf32(acc[mf][nf], a0, a1, a2, a3,
                                 __float_as_uint(bF[nf][2*j2]),
                                 __float_as_uint(bF[nf][2*j2+1]));
                        mma_tf32(acc2[mf][nf], a0, a1, a2, a3,
                                 __float_as_uint(bF[nf+2][2*j2]),
                                 __float_as_uint(bF[nf+2][2*j2+1]));
                    }
                }
            }
        }

        if (kc < 7) {
            float* Aw = As + ((kc + 1) & 1) * ABUF;
            float* Bw = Bs + ((kc + 1) & 1) * BBUF;
            #pragma unroll
            for (int i = 0; i < 4; ++i)
                *reinterpret_cast<float4*>(Aw + Adst[i]) = pa[i];
            #pragma unroll
            for (int i = 0; i < 2; ++i)
                *reinterpret_cast<float4*>(Bw + Bdst[i]) = pb[i];
            __syncthreads();
        }
    }

    #pragma unroll
    for (int mf = 0; mf < 2; ++mf) {
        const int row = bm + wm + mf * 16 + g;
        #pragma unroll
        for (int nf = 0; nf < 4; ++nf) {
            const float4 v = (nf < 2) ? acc[mf][nf] : acc2[mf][nf - 2];
            const int col = bn + wn + nf * 8 + c * 2;
            const float b0 = bias[col];
            const float b1 = bias[col + 1];
            if (row < M_ROWS) {
                float2 o = make_float2(v.x + b0, v.y + b1);
                *reinterpret_cast<float2*>(C + (size_t)row * N + col) = o;
            }
            if (row + 8 < M_ROWS) {
                float2 o = make_float2(v.z + b0, v.w + b1);
                *reinterpret_cast<float2*>(C + (size_t)(row + 8) * N + col) = o;
            }
        }
    }
}

__global__ __launch_bounds__(256, 2) void gemm_fused3_tc(
    const float* __restrict__ gvp, const float* __restrict__ gqp,
    const float* __restrict__ gwp,
    const float* __restrict__ bv, const float* __restrict__ boff,
    const float* __restrict__ battn,
    float* __restrict__ pv, float* __restrict__ poff, float* __restrict__ pattn)
{
    extern __shared__ float smem[];
    float* As = smem;
    float* Bs = smem + 2 * ABUF;
    const int id = blockIdx.x;
    const float *A, *W, *bias; float* C; int N, local;
    if (id < 4 * GM)      { A = gvp; W = gwp;             bias = bv;    C = pv;    N = 256; local = id; }
    else if (id < 8 * GM) { A = gqp; W = gwp + 256 * 256; bias = boff;  C = poff;  N = 256; local = id - 4*GM; }
    else                  { A = gqp; W = gwp + 512 * 256; bias = battn; C = pattn; N = 128; local = id - 8*GM; }
    const int gx = N / TBN;
    const int by = local / gx;
    const int bx = local - by * gx;
    gemm_tile(A, W, bias, C, N, by * TBM, bx * TBN, As, Bs);
}

__global__ __launch_bounds__(256, 2) void gemm_out_tc(
    const float* __restrict__ gmidp, const float* __restrict__ gwp,
    const float* __restrict__ bias, float* __restrict__ C)
{
    extern __shared__ float smem[];
    float* As = smem;
    float* Bs = smem + 2 * ABUF;
    const int by = blockIdx.x >> 2;
    const int bx = blockIdx.x & 3;
    gemm_tile(gmidp, gwp + 640 * 256, bias, C, 256, by * TBM, bx * TBN, As, Bs);
}

// ---------------- sampling kernel ----------------
// Phase 1 (lanes 0-15): softmax + 4 (weight,index) corner entries -> smem.
// Phase 2: 4-way split warp — quarter q takes corner q of every point; each
// lane gathers a float4 (4 channels) per corner (LDG.128). Two shfl rounds
// recombine; lanes 0-7 write the permuted-tf32 output.
__global__ __launch_bounds__(256) void sample_kernel(
    const float* __restrict__ v,
    const float* __restrict__ off,
    const float* __restrict__ attn,
    const float* __restrict__ ref,
    const int*   __restrict__ shapes,
    const float* __restrict__ zeta,
    float*       __restrict__ outp)   // permuted tf32 mid
{
    __shared__ float2 ent[8 * 64];

    const int m    = blockIdx.x;
    const int warp = threadIdx.x >> 5;
    const int lane = threadIdx.x & 31;
    const int b    = (m >= LQ) ? 1 : 0;

    const int p   = lane & 15;
    const int lvl = p >> 2;

    const float* attnp = attn + (size_t)m * 128 + warp * 16;
    float logit = attnp[p];
    float mx = logit;
    #pragma unroll
    for (int o = 8; o; o >>= 1) mx = fmaxf(mx, __shfl_xor_sync(0xffffffffu, mx, o));
    float e = __expf(logit - mx);
    float ssum = e;
    #pragma unroll
    for (int o = 8; o; o >>= 1) ssum += __shfl_xor_sync(0xffffffffu, ssum, o);
    const float a = e / ssum;

    if (lane < 16) {
        const int h0 = shapes[0], w0 = shapes[1];
        const int h1 = shapes[2], w1 = shapes[3];
        const int h2 = shapes[4], w2 = shapes[5];
        const int h3 = shapes[6], w3 = shapes[7];
        const int s1 = h0 * w0;
        const int s2 = s1 + h1 * w1;
        const int s3 = s2 + h2 * w2;

        const int H     = (lvl == 0) ? h0 : (lvl == 1) ? h1 : (lvl == 2) ? h2 : h3;
        const int W     = (lvl == 0) ? w0 : (lvl == 1) ? w1 : (lvl == 2) ? w2 : w3;
        const int start = (lvl == 0) ? 0  : (lvl == 1) ? s1 : (lvl == 2) ? s2 : s3;

        const float rx = ref[((size_t)m * NLVL + lvl) * 2 + 0];
        const float ry = ref[((size_t)m * NLVL + lvl) * 2 + 1];
        const float* offp = off + (size_t)m * 256 + warp * 32;
        const float ox = offp[2 * p + 0];
        const float oy = offp[2 * p + 1];

        const float x = fmaf(rx, (float)W, ox) - 0.5f;
        const float y = fmaf(ry, (float)H, oy) - 0.5f;
        const float x0f = floorf(x);
        const float y0f = floorf(y);
        const float wx = x - x0f;
        const float wy = y - y0f;
        const int x0 = (int)x0f;
        const int y0 = (int)y0f;

        const bool vx0 = (x0 >= 0)     && (x0 < W);
        const bool vx1 = (x0 + 1 >= 0) && (x0 + 1 < W);
        const bool vy0 = (y0 >= 0)     && (y0 < H);
        const bool vy1 = (y0 + 1 >= 0) && (y0 + 1 < H);

        const int x0c = min(max(x0, 0), W - 1);
        const int x1c = min(max(x0 + 1, 0), W - 1);
        const int y0c = min(max(y0, 0), H - 1);
        const int y1c = min(max(y0 + 1, 0), H - 1);

        const float w00 = (vx0 && vy0) ? (1.f - wx) * (1.f - wy) * a : 0.f;
        const float w01 = (vx1 && vy0) ? wx * (1.f - wy) * a : 0.f;
        const float w10 = (vx0 && vy1) ? (1.f - wx) * wy * a : 0.f;
        const float w11 = (vx1 && vy1) ? wx * wy * a : 0.f;

        const int rowbase = b * LV + start;
        const int hoff    = warp * 32;
        const int i00 = ((rowbase + y0c * W + x0c) << 8) + hoff;
        const int i01 = ((rowbase + y0c * W + x1c) << 8) + hoff;
        const int i10 = ((rowbase + y1c * W + x0c) << 8) + hoff;
        const int i11 = ((rowbase + y1c * W + x1c) << 8) + hoff;

        float2* ep = ent + warp * 64 + p * 4;
        ep[0] = make_float2(w00, __int_as_float(i00));
        ep[1] = make_float2(w01, __int_as_float(i01));
        ep[2] = make_float2(w10, __int_as_float(i10));
        ep[3] = make_float2(w11, __int_as_float(i11));
    }
    __syncwarp();

    // ---- phase 2: 4-way split, float4 gathers ----
    const int quarter = lane >> 3;       // corner id
    const int ql      = lane & 7;        // channel-quad owner
    const float2* eptr = ent + warp * 64 + quarter;
    const float* vbase = v + 4 * ql;

    float4 acc = make_float4(0.f, 0.f, 0.f, 0.f);
    #pragma unroll
    for (int i = 0; i < 16; ++i) {       // points
        const float2 eentry = eptr[4 * i];
        const float4 val = *reinterpret_cast<const float4*>(
            vbase + __float_as_int(eentry.y));
        acc.x = fmaf(eentry.x, val.x, acc.x);
        acc.y = fmaf(eentry.x, val.y, acc.y);
        acc.z = fmaf(eentry.x, val.z, acc.z);
        acc.w = fmaf(eentry.x, val.w, acc.w);
    }
    #pragma unroll
    for (int o = 16; o >= 8; o >>= 1) {
        acc.x += __shfl_down_sync(0xffffffffu, acc.x, o);
        acc.y += __shfl_down_sync(0xffffffffu, acc.y, o);
        acc.z += __shfl_down_sync(0xffffffffu, acc.z, o);
        acc.w += __shfl_down_sync(0xffffffffu, acc.w, o);
    }

    if (lane < 8) {
        // channels kl = 4*ql + j; permuted tf32: q = ql, comp = j
        // dst = m*256 + warp*32 + j*8 + ql
        const float4 z = *reinterpret_cast<const float4*>(zeta + 4 * ql);
        float* dst = outp + (size_t)m * 256 + warp * 32 + ql;
        dst[0]  = __uint_as_float(f2tf(acc.x * z.x));
        dst[8]  = __uint_as_float(f2tf(acc.y * z.y));
        dst[16] = __uint_as_float(f2tf(acc.z * z.z));
        dst[24] = __uint_as_float(f2tf(acc.w * z.w));
    }
}

// ---------------- launch ----------------
extern "C" void kernel_launch(void* const* d_in, const int* in_sizes, int n_in,
                              void* d_out, int out_size)
{
    const float* query  = (const float*)d_in[0];
    const float* ref    = (const float*)d_in[1];
    const float* value  = (const float*)d_in[2];
    const int*   shapes = (const int*)  d_in[3];
    const float* Wv     = (const float*)d_in[4];
    const float* bv     = (const float*)d_in[5];
    const float* Woff   = (const float*)d_in[6];
    const float* boff   = (const float*)d_in[7];
    const float* Wattn  = (const float*)d_in[8];
    const float* battn  = (const float*)d_in[9];
    const float* Wout   = (const float*)d_in[10];
    const float* bout   = (const float*)d_in[11];
    const float* zeta   = (const float*)d_in[12];
    float*       outp   = (float*)d_out;

    float *pv, *poff, *pattn, *pvp, *pqp, *pmidp, *pwp;
    cudaGetSymbolAddress((void**)&pv,    g_v);
    cudaGetSymbolAddress((void**)&poff,  g_off);
    cudaGetSymbolAddress((void**)&pattn, g_attn);
    cudaGetSymbolAddress((void**)&pvp,   g_vp);
    cudaGetSymbolAddress((void**)&pqp,   g_qp);
    cudaGetSymbolAddress((void**)&pmidp, g_midp);
    cudaGetSymbolAddress((void**)&pwp,   g_wp);

    cudaFuncSetAttribute(gemm_fused3_tc,
        cudaFuncAttributeMaxDynamicSharedMemorySize, (int)SMEM_BYTES);
    cudaFuncSetAttribute(gemm_out_tc,
        cudaFuncAttributeMaxDynamicSharedMemorySize, (int)SMEM_BYTES);

    prep_w<<<896, 64>>>(Wv, Woff, Wattn, Wout, pwp);
    prep_a<<<2080, 256>>>(value, query, pvp, pqp);
    gemm_fused3_tc<<<10 * GM, 256, SMEM_BYTES>>>(pvp, pqp, pwp, bv, boff, battn,
                                                 pv, poff, pattn);
    sample_kernel<<<M_ROWS, 256>>>(pv, poff, pattn, ref, shapes, zeta, pmidp);
    gemm_out_tc<<<4 * GM, 256, SMEM_BYTES>>>(pmidp, pwp, bout, outp);
}

// round 8
// speedup vs baseline: 2.9290x; 1.0208x over previous
#include <cuda_runtime.h>
#include <cuda_fp16.h>
#include <cstdint>
#include <math.h>

// ---------------- problem constants ----------------
constexpr int BS      = 2;
constexpr int LQ      = 13294;
constexpr int LV      = 13294;
constexpr int EMB     = 256;
constexpr int NLVL    = 4;
constexpr int M_ROWS  = BS * LQ;   // 26588

// ---------------- scratch ----------------
__device__ __half g_vh  [(size_t)M_ROWS * EMB];   // value-proj out, half, planar [head][row][32]
__device__ float  g_off [(size_t)M_ROWS * EMB];   // offsets out (fp32, plain)
__device__ float  g_attn[(size_t)M_ROWS * 128];   // attn logits (fp32, plain)
__device__ float  g_vp  [(size_t)M_ROWS * EMB];   // value input, tf32 permuted
__device__ float  g_qp  [(size_t)M_ROWS * EMB];   // query input, tf32 permuted
__device__ float  g_midp[(size_t)M_ROWS * EMB];   // sampled mid, tf32 permuted
__device__ float  g_wp  [(size_t)896 * EMB];      // all weights, tf32 permuted

// ---------------- GEMM config ----------------
constexpr int TBM   = 128;
constexpr int TBN   = 64;
constexpr int SROW  = 44;
constexpr int ABUF  = TBM * SROW;                 // floats
constexpr int BBUF  = TBN * SROW;
constexpr int STAGE = ABUF + BBUF;                // floats per stage
constexpr int GM    = (M_ROWS + TBM - 1) / TBM;   // 208
constexpr size_t SMEM_BYTES = (size_t)3 * STAGE * sizeof(float);

__device__ __forceinline__ unsigned f2tf(float x) {
    unsigned r;
    asm("cvt.rna.tf32.f32 %0, %1;" : "=r"(r) : "f"(x));
    return r;
}

__device__ __forceinline__ void mma_tf32(float4& d,
    unsigned a0, unsigned a1, unsigned a2, unsigned a3,
    unsigned b0, unsigned b1)
{
    asm volatile(
        "mma.sync.aligned.m16n8k8.row.col.f32.tf32.tf32.f32 "
        "{%0,%1,%2,%3},{%4,%5,%6,%7},{%8,%9},{%0,%1,%2,%3};"
        : "+f"(d.x), "+f"(d.y), "+f"(d.z), "+f"(d.w)
        : "r"(a0), "r"(a1), "r"(a2), "r"(a3), "r"(b0), "r"(b1));
}

__device__ __forceinline__ void cp16(uint32_t dst, const float* src) {
    asm volatile("cp.async.cg.shared.global [%0], [%1], 16;" :: "r"(dst), "l"(src));
}
__device__ __forceinline__ void cp_commit() {
    asm volatile("cp.async.commit_group;");
}
__device__ __forceinline__ void cp_wait1() {
    asm volatile("cp.async.wait_group 1;");
}
__device__ __forceinline__ void cp_wait0() {
    asm volatile("cp.async.wait_group 0;");
}

// ---------------- prep kernels ----------------
__global__ __launch_bounds__(64) void prep_w(
    const float* __restrict__ Wv,   const float* __restrict__ Woff,
    const float* __restrict__ Wattn,const float* __restrict__ Wout,
    float* __restrict__ gwp)
{
    const int r = blockIdx.x;
    const int t = threadIdx.x;
    const float* src; int lr;
    if (r < 256)      { src = Wv;    lr = r; }
    else if (r < 512) { src = Woff;  lr = r - 256; }
    else if (r < 640) { src = Wattn; lr = r - 512; }
    else              { src = Wout;  lr = r - 640; }
    const float4 v = *reinterpret_cast<const float4*>(src + (size_t)lr * 256 + t * 4);
    const int kc = t >> 3, q = t & 7;
    float* d = gwp + (size_t)r * 256 + kc * 32 + q;
    d[0]  = __uint_as_float(f2tf(v.x));
    d[8]  = __uint_as_float(f2tf(v.y));
    d[16] = __uint_as_float(f2tf(v.z));
    d[24] = __uint_as_float(f2tf(v.w));
}

__global__ __launch_bounds__(256) void prep_a(
    const float* __restrict__ value, const float* __restrict__ query,
    float* __restrict__ gvp, float* __restrict__ gqp)
{
    const int total = 2 * M_ROWS * 64;
    for (int f = blockIdx.x * blockDim.x + threadIdx.x; f < total;
         f += gridDim.x * blockDim.x) {
        int row = f >> 6;
        const int t = f & 63;
        const float* src; float* dst;
        if (row < M_ROWS) { src = value; dst = gvp; }
        else              { src = query; dst = gqp; row -= M_ROWS; }
        const float4 v = *reinterpret_cast<const float4*>(
            src + (size_t)row * 256 + t * 4);
        const int kc = t >> 3, q = t & 7;
        float* d = dst + (size_t)row * 256 + kc * 32 + q;
        d[0]  = __uint_as_float(f2tf(v.x));
        d[8]  = __uint_as_float(f2tf(v.y));
        d[16] = __uint_as_float(f2tf(v.z));
        d[24] = __uint_as_float(f2tf(v.w));
    }
}

// ---------------- GEMM tile body (cp.async 3-stage) ----------------
template<bool WRITE_HALF>
__device__ __forceinline__ void gemm_tile(
    const float* __restrict__ A, const float* __restrict__ Wp,
    const float* __restrict__ bias, float* __restrict__ C,
    __half* __restrict__ Ch,
    int N, int bm, int bn, float* smem)
{
    const int tid  = threadIdx.x;
    const int warp = tid >> 5;
    const int lane = tid & 31;
    const int g    = lane >> 2;
    const int c    = lane & 3;
    const int wm   = (warp >> 1) * 32;
    const int wn   = (warp & 1)  * 32;

    // staging coordinates
    const float* Aptr[4]; uint32_t AdstB[4];
    #pragma unroll
    for (int i = 0; i < 4; ++i) {
        const int f = tid + i * 256;
        const int row = f >> 3, s = f & 7;
        Aptr[i]  = A + (size_t)min(bm + row, M_ROWS - 1) * 256 + s * 4;
        AdstB[i] = (uint32_t)(row * SROW + s * 4) * 4u;
    }
    const float* Wptr[2]; uint32_t BdstB[2];
    #pragma unroll
    for (int i = 0; i < 2; ++i) {
        const int f = tid + i * 256;
        const int row = f >> 3, s = f & 7;
        Wptr[i]  = Wp + (size_t)(bn + row) * 256 + s * 4;
        BdstB[i] = (uint32_t)(ABUF + row * SROW + s * 4) * 4u;
    }
    const uint32_t smem_u32 = (uint32_t)__cvta_generic_to_shared(smem);
    constexpr uint32_t STGB = (uint32_t)STAGE * 4u;

    float4 acc[2][2], acc2[2][2];
    #pragma unroll
    for (int mf = 0; mf < 2; ++mf)
        #pragma unroll
        for (int nf = 0; nf < 2; ++nf) {
            acc[mf][nf]  = make_float4(0.f, 0.f, 0.f, 0.f);
            acc2[mf][nf] = make_float4(0.f, 0.f, 0.f, 0.f);
        }

    // prologue: issue chunks 0,1
    #pragma unroll
    for (int ck = 0; ck < 2; ++ck) {
        const int k0 = ck * 32;
        const uint32_t base = smem_u32 + ck * STGB;
        #pragma unroll
        for (int i = 0; i < 4; ++i) cp16(base + AdstB[i], Aptr[i] + k0);
        #pragma unroll
        for (int i = 0; i < 2; ++i) cp16(base + BdstB[i], Wptr[i] + k0);
        cp_commit();
    }
    cp_wait1();
    __syncthreads();

    int s_comp = 0, s_issue = 2;
    #pragma unroll 1
    for (int kc = 0; kc < 8; ++kc) {
        if (kc + 2 < 8) {
            const int k0 = (kc + 2) * 32;
            const uint32_t base = smem_u32 + s_issue * STGB;
            #pragma unroll
            for (int i = 0; i < 4; ++i) cp16(base + AdstB[i], Aptr[i] + k0);
            #pragma unroll
            for (int i = 0; i < 2; ++i) cp16(base + BdstB[i], Wptr[i] + k0);
            cp_commit();
            if (++s_issue == 3) s_issue = 0;
        }

        const float* Ab = smem + s_comp * STAGE;
        const float* Bb = Ab + ABUF;
        if (++s_comp == 3) s_comp = 0;

        #pragma unroll
        for (int half = 0; half < 2; ++half) {
            float aF[4][4];
            float bF[4][4];
            #pragma unroll
            for (int ri = 0; ri < 4; ++ri)
                *reinterpret_cast<float4*>(aF[ri]) =
                    *reinterpret_cast<const float4*>(
                        Ab + (wm + g + ri * 8) * SROW + c * 8 + half * 4);
            #pragma unroll
            for (int nf = 0; nf < 4; ++nf)
                *reinterpret_cast<float4*>(bF[nf]) =
                    *reinterpret_cast<const float4*>(
                        Bb + (wn + g + nf * 8) * SROW + c * 8 + half * 4);

            #pragma unroll
            for (int j2 = 0; j2 < 2; ++j2) {
                #pragma unroll
                for (int mf = 0; mf < 2; ++mf) {
                    const unsigned a0 = __float_as_uint(aF[2*mf  ][2*j2  ]);
                    const unsigned a1 = __float_as_uint(aF[2*mf+1][2*j2  ]);
                    const unsigned a2 = __float_as_uint(aF[2*mf  ][2*j2+1]);
                    const unsigned a3 = __float_as_uint(aF[2*mf+1][2*j2+1]);
                    #pragma unroll
                    for (int nf = 0; nf < 2; ++nf) {
                        mma_tf32(acc[mf][nf], a0, a1, a2, a3,
                                 __float_as_uint(bF[nf][2*j2]),
                                 __float_as_uint(bF[nf][2*j2+1]));
                        mma_tf32(acc2[mf][nf], a0, a1, a2, a3,
                                 __float_as_uint(bF[nf+2][2*j2]),
                                 __float_as_uint(bF[nf+2][2*j2+1]));
                    }
                }
            }
        }

        if (kc < 7) {
            if (kc + 2 < 8) cp_wait1(); else cp_wait0();
            __syncthreads();
        }
    }

    // epilogue with bias
    #pragma unroll
    for (int mf = 0; mf < 2; ++mf) {
        const int row = bm + wm + mf * 16 + g;
        #pragma unroll
        for (int nf = 0; nf < 4; ++nf) {
            const float4 v = (nf < 2) ? acc[mf][nf] : acc2[mf][nf - 2];
            const int col = bn + wn + nf * 8 + c * 2;
            const float b0 = bias[col];
            const float b1 = bias[col + 1];
            if (WRITE_HALF) {
                const int head = col >> 5, ch = col & 31;
                __half* base = Ch + ((size_t)head * M_ROWS) * 32 + ch;
                if (row < M_ROWS)
                    *reinterpret_cast<__half2*>(base + (size_t)row * 32) =
                        __float22half2_rn(make_float2(v.x + b0, v.y + b1));
                if (row + 8 < M_ROWS)
                    *reinterpret_cast<__half2*>(base + (size_t)(row + 8) * 32) =
                        __float22half2_rn(make_float2(v.z + b0, v.w + b1));
            } else {
                if (row < M_ROWS) {
                    float2 o = make_float2(v.x + b0, v.y + b1);
                    *reinterpret_cast<float2*>(C + (size_t)row * N + col) = o;
                }
                if (row + 8 < M_ROWS) {
                    float2 o = make_float2(v.z + b0, v.w + b1);
                    *reinterpret_cast<float2*>(C + (size_t)(row + 8) * N + col) = o;
                }
            }
        }
    }
}

__global__ __launch_bounds__(256, 2) void gemm_fused3_tc(
    const float* __restrict__ gvp, const float* __restrict__ gqp,
    const float* __restrict__ gwp,
    const float* __restrict__ bv, const float* __restrict__ boff,
    const float* __restrict__ battn,
    __half* __restrict__ pvh, float* __restrict__ poff, float* __restrict__ pattn)
{
    extern __shared__ float smem[];
    const int id = blockIdx.x;
    if (id < 4 * GM) {
        const int by = id >> 2, bx = id & 3;
        gemm_tile<true>(gvp, gwp, bv, nullptr, pvh, 256,
                        by * TBM, bx * TBN, smem);
    } else if (id < 8 * GM) {
        const int local = id - 4 * GM;
        const int by = local >> 2, bx = local & 3;
        gemm_tile<false>(gqp, gwp + 256 * 256, boff, poff, nullptr, 256,
                         by * TBM, bx * TBN, smem);
    } else {
        const int local = id - 8 * GM;
        const int by = local >> 1, bx = local & 1;
        gemm_tile<false>(gqp, gwp + 512 * 256, battn, pattn, nullptr, 128,
                         by * TBM, bx * TBN, smem);
    }
}

__global__ __launch_bounds__(256, 2) void gemm_out_tc(
    const float* __restrict__ gmidp, const float* __restrict__ gwp,
    const float* __restrict__ bias, float* __restrict__ C)
{
    extern __shared__ float smem[];
    const int by = blockIdx.x >> 2;
    const int bx = blockIdx.x & 3;
    gemm_tile<false>(gmidp, gwp + 640 * 256, bias, C, nullptr, 256,
                     by * TBM, bx * TBN, smem);
}

// ---------------- sampling kernel ----------------
// Values now half, head-planar: g_vh[head][b*LV + spatial][32].
// Phase 1 (lanes 0-15): softmax + 4 (weight, byte-offset) corner entries.
// Phase 2: quarter q = corner q; lane loads half4 (8B); x-adjacent corners
// are contiguous 64B rows -> x-pairs share a 128B line.
__global__ __launch_bounds__(256) void sample_kernel(
    const __half* __restrict__ vh,
    const float* __restrict__ off,
    const float* __restrict__ attn,
    const float* __restrict__ ref,
    const int*   __restrict__ shapes,
    const float* __restrict__ zeta,
    float*       __restrict__ outp)   // permuted tf32 mid
{
    __shared__ float2 ent[8 * 64];

    const int m    = blockIdx.x;
    const int warp = threadIdx.x >> 5;
    const int lane = threadIdx.x & 31;
    const int b    = (m >= LQ) ? 1 : 0;

    const int p   = lane & 15;
    const int lvl = p >> 2;

    const float* attnp = attn + (size_t)m * 128 + warp * 16;
    float logit = attnp[p];
    float mx = logit;
    #pragma unroll
    for (int o = 8; o; o >>= 1) mx = fmaxf(mx, __shfl_xor_sync(0xffffffffu, mx, o));
    float e = __expf(logit - mx);
    float ssum = e;
    #pragma unroll
    for (int o = 8; o; o >>= 1) ssum += __shfl_xor_sync(0xffffffffu, ssum, o);
    const float a = e / ssum;

    if (lane < 16) {
        const int h0 = shapes[0], w0 = shapes[1];
        const int h1 = shapes[2], w1 = shapes[3];
        const int h2 = shapes[4], w2 = shapes[5];
        const int h3 = shapes[6], w3 = shapes[7];
        const int s1 = h0 * w0;
        const int s2 = s1 + h1 * w1;
        const int s3 = s2 + h2 * w2;

        const int H     = (lvl == 0) ? h0 : (lvl == 1) ? h1 : (lvl == 2) ? h2 : h3;
        const int W     = (lvl == 0) ? w0 : (lvl == 1) ? w1 : (lvl == 2) ? w2 : w3;
        const int start = (lvl == 0) ? 0  : (lvl == 1) ? s1 : (lvl == 2) ? s2 : s3;

        const float rx = ref[((size_t)m * NLVL + lvl) * 2 + 0];
        const float ry = ref[((size_t)m * NLVL + lvl) * 2 + 1];
        const float* offp = off + (size_t)m * 256 + warp * 32;
        const float ox = offp[2 * p + 0];
        const float oy = offp[2 * p + 1];

        const float x = fmaf(rx, (float)W, ox) - 0.5f;
        const float y = fmaf(ry, (float)H, oy) - 0.5f;
        const float x0f = floorf(x);
        const float y0f = floorf(y);
        const float wx = x - x0f;
        const float wy = y - y0f;
        const int x0 = (int)x0f;
        const int y0 = (int)y0f;

        const bool vx0 = (x0 >= 0)     && (x0 < W);
        const bool vx1 = (x0 + 1 >= 0) && (x0 + 1 < W);
        const bool vy0 = (y0 >= 0)     && (y0 < H);
        const bool vy1 = (y0 + 1 >= 0) && (y0 + 1 < H);

        const int x0c = min(max(x0, 0), W - 1);
        const int x1c = min(max(x0 + 1, 0), W - 1);
        const int y0c = min(max(y0, 0), H - 1);
        const int y1c = min(max(y0 + 1, 0), H - 1);

        const float w00 = (vx0 && vy0) ? (1.f - wx) * (1.f - wy) * a : 0.f;
        const float w01 = (vx1 && vy0) ? wx * (1.f - wy) * a : 0.f;
        const float w10 = (vx0 && vy1) ? (1.f - wx) * wy * a : 0.f;
        const float w11 = (vx1 && vy1) ? wx * wy * a : 0.f;

        const int rowbase = b * LV + start;
        // byte offset within head plane: row * 64
        const int i00 = (rowbase + y0c * W + x0c) << 6;
        const int i01 = (rowbase + y0c * W + x1c) << 6;
        const int i10 = (rowbase + y1c * W + x0c) << 6;
        const int i11 = (rowbase + y1c * W + x1c) << 6;

        float2* ep = ent + warp * 64 + p * 4;
        ep[0] = make_float2(w00, __int_as_float(i00));
        ep[1] = make_float2(w01, __int_as_float(i01));
        ep[2] = make_float2(w10, __int_as_float(i10));
        ep[3] = make_float2(w11, __int_as_float(i11));
    }
    __syncwarp();

    // ---- phase 2: 4-way split, half4 gathers ----
    const int quarter = lane >> 3;       // corner id
    const int ql      = lane & 7;        // channel-quad owner
    const float2* eptr = ent + warp * 64 + quarter;
    const char* hb = reinterpret_cast<const char*>(
        vh + ((size_t)warp * M_ROWS) * 32) + 8 * ql;

    float4 acc = make_float4(0.f, 0.f, 0.f, 0.f);
    #pragma unroll
    for (int i = 0; i < 16; ++i) {       // points
        const float2 eentry = eptr[4 * i];
        const uint2 u = *reinterpret_cast<const uint2*>(
            hb + __float_as_int(eentry.y));
        const float2 f01 = __half22float2(*reinterpret_cast<const __half2*>(&u.x));
        const float2 f23 = __half22float2(*reinterpret_cast<const __half2*>(&u.y));
        acc.x = fmaf(eentry.x, f01.x, acc.x);
        acc.y = fmaf(eentry.x, f01.y, acc.y);
        acc.z = fmaf(eentry.x, f23.x, acc.z);
        acc.w = fmaf(eentry.x, f23.y, acc.w);
    }
    #pragma unroll
    for (int o = 16; o >= 8; o >>= 1) {
        acc.x += __shfl_down_sync(0xffffffffu, acc.x, o);
        acc.y += __shfl_down_sync(0xffffffffu, acc.y, o);
        acc.z += __shfl_down_sync(0xffffffffu, acc.z, o);
        acc.w += __shfl_down_sync(0xffffffffu, acc.w, o);
    }

    if (lane < 8) {
        // channels kl = 4*ql + j; permuted tf32: q = ql, comp = j
        const float4 z = *reinterpret_cast<const float4*>(zeta + 4 * ql);
        float* dst = outp + (size_t)m * 256 + warp * 32 + ql;
        dst[0]  = __uint_as_float(f2tf(acc.x * z.x));
        dst[8]  = __uint_as_float(f2tf(acc.y * z.y));
        dst[16] = __uint_as_float(f2tf(acc.z * z.z));
        dst[24] = __uint_as_float(f2tf(acc.w * z.w));
    }
}

// ---------------- launch ----------------
extern "C" void kernel_launch(void* const* d_in, const int* in_sizes, int n_in,
                              void* d_out, int out_size)
{
    const float* query  = (const float*)d_in[0];
    const float* ref    = (const float*)d_in[1];
    const float* value  = (const float*)d_in[2];
    const int*   shapes = (const int*)  d_in[3];
    const float* Wv     = (const float*)d_in[4];
    const float* bv     = (const float*)d_in[5];
    const float* Woff   = (const float*)d_in[6];
    const float* boff   = (const float*)d_in[7];
    const float* Wattn  = (const float*)d_in[8];
    const float* battn  = (const float*)d_in[9];
    const float* Wout   = (const float*)d_in[10];
    const float* bout   = (const float*)d_in[11];
    const float* zeta   = (const float*)d_in[12];
    float*       outp   = (float*)d_out;

    float *poff, *pattn, *pvp, *pqp, *pmidp, *pwp;
    __half* pvh;
    cudaGetSymbolAddress((void**)&pvh,   g_vh);
    cudaGetSymbolAddress((void**)&poff,  g_off);
    cudaGetSymbolAddress((void**)&pattn, g_attn);
    cudaGetSymbolAddress((void**)&pvp,   g_vp);
    cudaGetSymbolAddress((void**)&pqp,   g_qp);
    cudaGetSymbolAddress((void**)&pmidp, g_midp);
    cudaGetSymbolAddress((void**)&pwp,   g_wp);

    cudaFuncSetAttribute(gemm_fused3_tc,
        cudaFuncAttributeMaxDynamicSharedMemorySize, (int)SMEM_BYTES);
    cudaFuncSetAttribute(gemm_out_tc,
        cudaFuncAttributeMaxDynamicSharedMemorySize, (int)SMEM_BYTES);

    prep_w<<<896, 64>>>(Wv, Woff, Wattn, Wout, pwp);
    prep_a<<<2080, 256>>>(value, query, pvp, pqp);
    gemm_fused3_tc<<<10 * GM, 256, SMEM_BYTES>>>(pvp, pqp, pwp, bv, boff, battn,
                                                 pvh, poff, pattn);
    sample_kernel<<<M_ROWS, 256>>>(pvh, poff, pattn, ref, shapes, zeta, pmidp);
    gemm_out_tc<<<4 * GM, 256, SMEM_BYTES>>>(pmidp, pwp, bout, outp);
}

// round 9
// speedup vs baseline: 4.0476x; 1.3819x over previous
#include <cuda_runtime.h>
#include <cuda_fp16.h>
#include <cstdint>
#include <math.h>

// ---------------- problem constants ----------------
constexpr int BS      = 2;
constexpr int LQ      = 13294;
constexpr int LV      = 13294;
constexpr int EMB     = 256;
constexpr int NLVL    = 4;
constexpr int M_ROWS  = BS * LQ;   // 26588

// ---------------- scratch ----------------
__device__ __half g_vh  [(size_t)M_ROWS * EMB];   // value-proj out, half, planar [head][row][32]
__device__ float  g_off [(size_t)M_ROWS * EMB];   // offsets out (fp32, plain)
__device__ float  g_attn[(size_t)M_ROWS * 128];   // attn logits (fp32, plain)
__device__ __half g_vp  [(size_t)M_ROWS * EMB];   // value input, half permuted
__device__ __half g_qp  [(size_t)M_ROWS * EMB];   // query input, half permuted
__device__ __half g_midp[(size_t)M_ROWS * EMB];   // sampled mid, half permuted
__device__ __half g_wp  [(size_t)896 * EMB];      // all weights, half permuted

// ---------------- GEMM config ----------------
// fp16 HMMA m16n8k16. Block tile 128(M) x 64(N), BK=32 halves, 256 thr.
// Permuted half layout per row: 8 chunks of 64B (kc), each 4x16B words-groups
// (chunk index c), word t of group c holds halves kl0=2c+8(t&1)+16(t>>1), kl0+1.
// Plain chunk order in global; XOR swizzle (c ^ row&3) applied at cp.async dst.
constexpr int TBM   = 128;
constexpr int TBN   = 64;
constexpr int ABYT  = TBM * 64;                   // A stage bytes (8192)
constexpr int BBYT  = TBN * 64;                   // B stage bytes (4096)
constexpr int STGB  = ABYT + BBYT;                // 12288
constexpr int GM    = (M_ROWS + TBM - 1) / TBM;   // 208
constexpr size_t SMEM_BYTES = (size_t)3 * STGB;

__device__ __forceinline__ void mma_f16(float4& d,
    unsigned a0, unsigned a1, unsigned a2, unsigned a3,
    unsigned b0, unsigned b1)
{
    asm volatile(
        "mma.sync.aligned.m16n8k16.row.col.f32.f16.f16.f32 "
        "{%0,%1,%2,%3},{%4,%5,%6,%7},{%8,%9},{%0,%1,%2,%3};"
        : "+f"(d.x), "+f"(d.y), "+f"(d.z), "+f"(d.w)
        : "r"(a0), "r"(a1), "r"(a2), "r"(a3), "r"(b0), "r"(b1));
}

__device__ __forceinline__ void cp16(uint32_t dst, const void* src) {
    asm volatile("cp.async.cg.shared.global [%0], [%1], 16;" :: "r"(dst), "l"(src));
}
__device__ __forceinline__ void cp_commit() { asm volatile("cp.async.commit_group;"); }
__device__ __forceinline__ void cp_wait1()  { asm volatile("cp.async.wait_group 1;"); }
__device__ __forceinline__ void cp_wait0()  { asm volatile("cp.async.wait_group 0;"); }

// ---------------- unified prep kernel ----------------
// rows 0..M-1: value -> g_vp; M..2M-1: query -> g_qp;
// 2M..2M+895: weights -> g_wp (0-255 Wv, 256-511 Woff, 512-639 Wattn, 640-895 Wout)
__global__ __launch_bounds__(256) void prep_all(
    const float* __restrict__ value, const float* __restrict__ query,
    const float* __restrict__ Wv,   const float* __restrict__ Woff,
    const float* __restrict__ Wattn,const float* __restrict__ Wout,
    __half* __restrict__ gv, __half* __restrict__ gq, __half* __restrict__ gw)
{
    const int task = blockIdx.x * blockDim.x + threadIdx.x;   // (row, kc)
    constexpr int NT = (2 * M_ROWS + 896) * 8;
    if (task >= NT) return;
    const int row = task >> 3;
    const int kc  = task & 7;

    const float* src; __half* dst; int lr;
    if (row < M_ROWS)            { src = value; dst = gv; lr = row; }
    else if (row < 2 * M_ROWS)   { src = query; dst = gq; lr = row - M_ROWS; }
    else {
        const int wr = row - 2 * M_ROWS;
        dst = gw; lr = wr;
        int sr;
        if (wr < 256)      { src = Wv;    sr = wr; }
        else if (wr < 512) { src = Woff;  sr = wr - 256; }
        else if (wr < 640) { src = Wattn; sr = wr - 512; }
        else               { src = Wout;  sr = wr - 640; }
        src += (size_t)sr * 256 - (size_t)lr * 256;   // fold into common index below
    }

    const float* sp = src + (size_t)lr * 256 + kc * 32;
    float f[32];
    #pragma unroll
    for (int i = 0; i < 8; ++i)
        *reinterpret_cast<float4*>(f + 4 * i) =
            *reinterpret_cast<const float4*>(sp + 4 * i);

    char* dp = reinterpret_cast<char*>(dst) + (size_t)lr * 512 + kc * 64;
    #pragma unroll
    for (int c = 0; c < 4; ++c) {
        uint32_t w[4];
        #pragma unroll
        for (int t = 0; t < 4; ++t) {
            const int kl0 = 2 * c + 8 * (t & 1) + 16 * (t >> 1);
            const __half2 h = __floats2half2_rn(f[kl0], f[kl0 + 1]);
            w[t] = *reinterpret_cast<const uint32_t*>(&h);
        }
        *reinterpret_cast<uint4*>(dp + c * 16) = make_uint4(w[0], w[1], w[2], w[3]);
    }
}

// ---------------- GEMM tile body (fp16, cp.async 3-stage) ----------------
template<bool WRITE_HALF_PLANAR>
__device__ __forceinline__ void gemm_tile(
    const __half* __restrict__ A, const __half* __restrict__ W,
    const float* __restrict__ bias, float* __restrict__ C,
    __half* __restrict__ Ch,
    int N, int bm, int bn, char* smem)
{
    const int tid  = threadIdx.x;
    const int warp = tid >> 5;
    const int lane = tid & 31;
    const int g    = lane >> 2;
    const int c    = lane & 3;
    const int wm   = (warp >> 1) * 32;
    const int wn   = (warp & 1)  * 32;

    // staging: A 512 chunks (2/thr), B 256 chunks (1/thr)
    const char* Asrc[2]; uint32_t Adst[2];
    #pragma unroll
    for (int i = 0; i < 2; ++i) {
        const int cid = tid + i * 256;
        const int row = cid >> 2, ch = cid & 3;
        Asrc[i] = reinterpret_cast<const char*>(A)
                + (size_t)min(bm + row, M_ROWS - 1) * 512 + ch * 16;
        Adst[i] = (uint32_t)(row * 64 + ((ch ^ (row & 3)) * 16));
    }
    const char* Bsrc; uint32_t Bdst;
    {
        const int row = tid >> 2, ch = tid & 3;
        Bsrc = reinterpret_cast<const char*>(W) + (size_t)(bn + row) * 512 + ch * 16;
        Bdst = (uint32_t)(ABYT + row * 64 + ((ch ^ (row & 3)) * 16));
    }
    const uint32_t smem_u32 = (uint32_t)__cvta_generic_to_shared(smem);

    float4 acc[2][4];
    #pragma unroll
    for (int mf = 0; mf < 2; ++mf)
        #pragma unroll
        for (int nf = 0; nf < 4; ++nf)
            acc[mf][nf] = make_float4(0.f, 0.f, 0.f, 0.f);

    // prologue: issue chunks 0,1
    #pragma unroll
    for (int ck = 0; ck < 2; ++ck) {
        const uint32_t base = smem_u32 + ck * STGB;
        cp16(base + Adst[0], Asrc[0] + ck * 64);
        cp16(base + Adst[1], Asrc[1] + ck * 64);
        cp16(base + Bdst,    Bsrc    + ck * 64);
        cp_commit();
    }
    cp_wait1();
    __syncthreads();

    const int cx = (c ^ (g & 3)) * 16;

    int s_comp = 0, s_issue = 2;
    #pragma unroll 1
    for (int kc = 0; kc < 8; ++kc) {
        if (kc + 2 < 8) {
            const uint32_t base = smem_u32 + s_issue * STGB;
            cp16(base + Adst[0], Asrc[0] + (kc + 2) * 64);
            cp16(base + Adst[1], Asrc[1] + (kc + 2) * 64);
            cp16(base + Bdst,    Bsrc    + (kc + 2) * 64);
            cp_commit();
            if (++s_issue == 3) s_issue = 0;
        }

        const char* Ab = smem + s_comp * STGB;
        const char* Bb = Ab + ABYT;
        if (++s_comp == 3) s_comp = 0;

        uint4 Ar[4], Br[4];
        #pragma unroll
        for (int ri = 0; ri < 4; ++ri)
            Ar[ri] = *reinterpret_cast<const uint4*>(Ab + (wm + g + ri * 8) * 64 + cx);
        #pragma unroll
        for (int nf = 0; nf < 4; ++nf)
            Br[nf] = *reinterpret_cast<const uint4*>(Bb + (wn + nf * 8 + g) * 64 + cx);

        #pragma unroll
        for (int st = 0; st < 2; ++st) {
            #pragma unroll
            for (int mf = 0; mf < 2; ++mf) {
                const unsigned a0 = st ? Ar[2*mf  ].z : Ar[2*mf  ].x;
                const unsigned a1 = st ? Ar[2*mf+1].z : Ar[2*mf+1].x;
                const unsigned a2 = st ? Ar[2*mf  ].w : Ar[2*mf  ].y;
                const unsigned a3 = st ? Ar[2*mf+1].w : Ar[2*mf+1].y;
                #pragma unroll
                for (int nf = 0; nf < 4; ++nf) {
                    const unsigned b0 = st ? Br[nf].z : Br[nf].x;
                    const unsigned b1 = st ? Br[nf].w : Br[nf].y;
                    mma_f16(acc[mf][nf], a0, a1, a2, a3, b0, b1);
                }
            }
        }

        if (kc < 7) {
            if (kc + 2 < 8) cp_wait1(); else cp_wait0();
            __syncthreads();
        }
    }

    // epilogue with bias
    #pragma unroll
    for (int mf = 0; mf < 2; ++mf) {
        const int row = bm + wm + mf * 16 + g;
        #pragma unroll
        for (int nf = 0; nf < 4; ++nf) {
            const float4 v = acc[mf][nf];
            const int col = bn + wn + nf * 8 + c * 2;
            const float b0 = bias[col];
            const float b1 = bias[col + 1];
            if (WRITE_HALF_PLANAR) {
                const int head = col >> 5, ch = col & 31;
                __half* base = Ch + ((size_t)head * M_ROWS) * 32 + ch;
                if (row < M_ROWS)
                    *reinterpret_cast<__half2*>(base + (size_t)row * 32) =
                        __floats2half2_rn(v.x + b0, v.y + b1);
                if (row + 8 < M_ROWS)
                    *reinterpret_cast<__half2*>(base + (size_t)(row + 8) * 32) =
                        __floats2half2_rn(v.z + b0, v.w + b1);
            } else {
                if (row < M_ROWS) {
                    float2 o = make_float2(v.x + b0, v.y + b1);
                    *reinterpret_cast<float2*>(C + (size_t)row * N + col) = o;
                }
                if (row + 8 < M_ROWS) {
                    float2 o = make_float2(v.z + b0, v.w + b1);
                    *reinterpret_cast<float2*>(C + (size_t)(row + 8) * N + col) = o;
                }
            }
        }
    }
}

__global__ __launch_bounds__(256, 2) void gemm_fused3_tc(
    const __half* __restrict__ gvp, const __half* __restrict__ gqp,
    const __half* __restrict__ gwp,
    const float* __restrict__ bv, const float* __restrict__ boff,
    const float* __restrict__ battn,
    __half* __restrict__ pvh, float* __restrict__ poff, float* __restrict__ pattn)
{
    extern __shared__ char smem[];
    const int id = blockIdx.x;
    if (id < 4 * GM) {
        const int by = id >> 2, bx = id & 3;
        gemm_tile<true>(gvp, gwp, bv, nullptr, pvh, 256,
                        by * TBM, bx * TBN, smem);
    } else if (id < 8 * GM) {
        const int local = id - 4 * GM;
        const int by = local >> 2, bx = local & 3;
        gemm_tile<false>(gqp, gwp + 256 * 256, boff, poff, nullptr, 256,
                         by * TBM, bx * TBN, smem);
    } else {
        const int local = id - 8 * GM;
        const int by = local >> 1, bx = local & 1;
        gemm_tile<false>(gqp, gwp + 512 * 256, battn, pattn, nullptr, 128,
                         by * TBM, bx * TBN, smem);
    }
}

__global__ __launch_bounds__(256, 2) void gemm_out_tc(
    const __half* __restrict__ gmidp, const __half* __restrict__ gwp,
    const float* __restrict__ bias, float* __restrict__ C)
{
    extern __shared__ char smem[];
    const int by = blockIdx.x >> 2;
    const int bx = blockIdx.x & 3;
    gemm_tile<false>(gmidp, gwp + 640 * 256, bias, C, nullptr, 256,
                     by * TBM, bx * TBN, smem);
}

// ---------------- sampling kernel ----------------
__global__ __launch_bounds__(256) void sample_kernel(
    const __half* __restrict__ vh,
    const float* __restrict__ off,
    const float* __restrict__ attn,
    const float* __restrict__ ref,
    const int*   __restrict__ shapes,
    const float* __restrict__ zeta,
    __half*      __restrict__ outp)   // permuted half mid
{
    __shared__ float2 ent[8 * 64];

    const int m    = blockIdx.x;
    const int warp = threadIdx.x >> 5;
    const int lane = threadIdx.x & 31;
    const int b    = (m >= LQ) ? 1 : 0;

    const int p   = lane & 15;
    const int lvl = p >> 2;

    const float* attnp = attn + (size_t)m * 128 + warp * 16;
    float logit = attnp[p];
    float mx = logit;
    #pragma unroll
    for (int o = 8; o; o >>= 1) mx = fmaxf(mx, __shfl_xor_sync(0xffffffffu, mx, o));
    float e = __expf(logit - mx);
    float ssum = e;
    #pragma unroll
    for (int o = 8; o; o >>= 1) ssum += __shfl_xor_sync(0xffffffffu, ssum, o);
    const float a = e / ssum;

    if (lane < 16) {
        const int h0 = shapes[0], w0 = shapes[1];
        const int h1 = shapes[2], w1 = shapes[3];
        const int h2 = shapes[4], w2 = shapes[5];
        const int h3 = shapes[6], w3 = shapes[7];
        const int s1 = h0 * w0;
        const int s2 = s1 + h1 * w1;
        const int s3 = s2 + h2 * w2;

        const int H     = (lvl == 0) ? h0 : (lvl == 1) ? h1 : (lvl == 2) ? h2 : h3;
        const int W     = (lvl == 0) ? w0 : (lvl == 1) ? w1 : (lvl == 2) ? w2 : w3;
        const int start = (lvl == 0) ? 0  : (lvl == 1) ? s1 : (lvl == 2) ? s2 : s3;

        const float rx = ref[((size_t)m * NLVL + lvl) * 2 + 0];
        const float ry = ref[((size_t)m * NLVL + lvl) * 2 + 1];
        const float* offp = off + (size_t)m * 256 + warp * 32;
        const float ox = offp[2 * p + 0];
        const float oy = offp[2 * p + 1];

        const float x = fmaf(rx, (float)W, ox) - 0.5f;
        const float y = fmaf(ry, (float)H, oy) - 0.5f;
        const float x0f = floorf(x);
        const float y0f = floorf(y);
        const float wx = x - x0f;
        const float wy = y - y0f;
        const int x0 = (int)x0f;
        const int y0 = (int)y0f;

        const bool vx0 = (x0 >= 0)     && (x0 < W);
        const bool vx1 = (x0 + 1 >= 0) && (x0 + 1 < W);
        const bool vy0 = (y0 >= 0)     && (y0 < H);
        const bool vy1 = (y0 + 1 >= 0) && (y0 + 1 < H);

        const int x0c = min(max(x0, 0), W - 1);
        const int x1c = min(max(x0 + 1, 0), W - 1);
        const int y0c = min(max(y0, 0), H - 1);
        const int y1c = min(max(y0 + 1, 0), H - 1);

        const float w00 = (vx0 && vy0) ? (1.f - wx) * (1.f - wy) * a : 0.f;
        const float w01 = (vx1 && vy0) ? wx * (1.f - wy) * a : 0.f;
        const float w10 = (vx0 && vy1) ? (1.f - wx) * wy * a : 0.f;
        const float w11 = (vx1 && vy1) ? wx * wy * a : 0.f;

        const int rowbase = b * LV + start;
        const int i00 = (rowbase + y0c * W + x0c) << 6;   // byte offset, 64B rows
        const int i01 = (rowbase + y0c * W + x1c) << 6;
        const int i10 = (rowbase + y1c * W + x0c) << 6;
        const int i11 = (rowbase + y1c * W + x1c) << 6;

        float2* ep = ent + warp * 64 + p * 4;
        ep[0] = make_float2(w00, __int_as_float(i00));
        ep[1] = make_float2(w01, __int_as_float(i01));
        ep[2] = make_float2(w10, __int_as_float(i10));
        ep[3] = make_float2(w11, __int_as_float(i11));
    }
    __syncwarp();

    // ---- phase 2: 4-way split, half4 gathers ----
    const int quarter = lane >> 3;
    const int ql      = lane & 7;
    const float2* eptr = ent + warp * 64 + quarter;
    const char* hb = reinterpret_cast<const char*>(
        vh + ((size_t)warp * M_ROWS) * 32) + 8 * ql;

    float4 acc = make_float4(0.f, 0.f, 0.f, 0.f);
    #pragma unroll
    for (int i = 0; i < 16; ++i) {
        const float2 eentry = eptr[4 * i];
        const uint2 u = *reinterpret_cast<const uint2*>(
            hb + __float_as_int(eentry.y));
        const float2 f01 = __half22float2(*reinterpret_cast<const __half2*>(&u.x));
        const float2 f23 = __half22float2(*reinterpret_cast<const __half2*>(&u.y));
        acc.x = fmaf(eentry.x, f01.x, acc.x);
        acc.y = fmaf(eentry.x, f01.y, acc.y);
        acc.z = fmaf(eentry.x, f23.x, acc.z);
        acc.w = fmaf(eentry.x, f23.y, acc.w);
    }
    #pragma unroll
    for (int o = 16; o >= 8; o >>= 1) {
        acc.x += __shfl_down_sync(0xffffffffu, acc.x, o);
        acc.y += __shfl_down_sync(0xffffffffu, acc.y, o);
        acc.z += __shfl_down_sync(0xffffffffu, acc.z, o);
        acc.w += __shfl_down_sync(0xffffffffu, acc.w, o);
    }

    if (lane < 8) {
        // channels kl = 4*ql + j; write permuted-half layout (plain chunk order)
        const float4 z = *reinterpret_cast<const float4*>(zeta + 4 * ql);
        char* base = reinterpret_cast<char*>(outp) + (size_t)m * 512 + warp * 64;

        const __half2 h01 = __floats2half2_rn(acc.x * z.x, acc.y * z.y);
        const __half2 h23 = __floats2half2_rn(acc.z * z.z, acc.w * z.w);

        const int kl0 = 4 * ql;
        const int c0 = (kl0 >> 1) & 3;
        const int t0 = ((kl0 >> 3) & 1) | (((kl0 >> 4) & 1) << 1);
        *reinterpret_cast<uint32_t*>(base + c0 * 16 + t0 * 4) =
            *reinterpret_cast<const uint32_t*>(&h01);

        const int kl2 = 4 * ql + 2;
        const int c2 = (kl2 >> 1) & 3;
        const int t2 = ((kl2 >> 3) & 1) | (((kl2 >> 4) & 1) << 1);
        *reinterpret_cast<uint32_t*>(base + c2 * 16 + t2 * 4) =
            *reinterpret_cast<const uint32_t*>(&h23);
    }
}

// ---------------- launch ----------------
extern "C" void kernel_launch(void* const* d_in, const int* in_sizes, int n_in,
                              void* d_out, int out_size)
{
    const float* query  = (const float*)d_in[0];
    const float* ref    = (const float*)d_in[1];
    const float* value  = (const float*)d_in[2];
    const int*   shapes = (const int*)  d_in[3];
    const float* Wv     = (const float*)d_in[4];
    const float* bv     = (const float*)d_in[5];
    const float* Woff   = (const float*)d_in[6];
    const float* boff   = (const float*)d_in[7];
    const float* Wattn  = (const float*)d_in[8];
    const float* battn  = (const float*)d_in[9];
    const float* Wout   = (const float*)d_in[10];
    const float* bout   = (const float*)d_in[11];
    const float* zeta   = (const float*)d_in[12];
    float*       outp   = (float*)d_out;

    float *poff, *pattn;
    __half *pvh, *pvp, *pqp, *pmidp, *pwp;
    cudaGetSymbolAddress((void**)&pvh,   g_vh);
    cudaGetSymbolAddress((void**)&poff,  g_off);
    cudaGetSymbolAddress((void**)&pattn, g_attn);
    cudaGetSymbolAddress((void**)&pvp,   g_vp);
    cudaGetSymbolAddress((void**)&pqp,   g_qp);
    cudaGetSymbolAddress((void**)&pmidp, g_midp);
    cudaGetSymbolAddress((void**)&pwp,   g_wp);

    const int NT = (2 * M_ROWS + 896) * 8;
    prep_all<<<(NT + 255) / 256, 256>>>(value, query, Wv, Woff, Wattn, Wout,
                                        pvp, pqp, pwp);
    gemm_fused3_tc<<<10 * GM, 256, SMEM_BYTES>>>(pvp, pqp, pwp, bv, boff, battn,
                                                 pvh, poff, pattn);
    sample_kernel<<<M_ROWS, 256>>>(pvh, poff, pattn, ref, shapes, zeta, pmidp);
    gemm_out_tc<<<4 * GM, 256, SMEM_BYTES>>>(pmidp, pwp, bout, outp);
}